// round 13
// baseline (speedup 1.0000x reference)
#include <cuda_runtime.h>
#include <math.h>
#include <stdint.h>

#define NB 8
#define NL 512
#define NE 128
#define NT1 129
#define NT2 513
#define M1R (NB*NT1)        // 1032
#define M2R (NB*NT2)        // 4104
#define MTR (M1R+M2R)       // 5136

// ---------------- device scratch ----------------
__device__ float g_Qb   [NB*NL*NE];
__device__ float g_Kb   [NB*NL*NE];
__device__ float g_Qc   [128*NE];
__device__ float g_o32a [NB*NL*32];
__device__ float g_o32c [NB*128*32];
__device__ float g_X    [MTR*128];
__device__ float g_Q    [MTR*128];
__device__ float g_K    [MTR*128];
__device__ float g_V    [MTR*128];
__device__ float g_X2   [MTR*128];

// ---------------- fast exp on FMA/ALU pipes (args <= 0) ----------------
__device__ __forceinline__ float fexp(float x)
{
    x = fmaxf(x, -80.0f);
    float t  = x * 1.4426950408889634f;
    float kf = t + 12582912.0f;
    int   k  = __float_as_int(kf) - 0x4B400000;
    float f  = t - (kf - 12582912.0f);
    float p  = 1.3333558e-3f;
    p = fmaf(p, f, 9.6181291e-3f);
    p = fmaf(p, f, 5.5504109e-2f);
    p = fmaf(p, f, 2.4022651e-1f);
    p = fmaf(p, f, 6.9314718e-1f);
    p = fmaf(p, f, 1.0f);
    return __int_as_float(__float_as_int(p) + (k << 23));
}

// ---------------- tf32 helpers ----------------
__device__ __forceinline__ float f2tf(float f)
{
    uint32_t r;
    asm("cvt.rna.tf32.f32 %0, %1;" : "=r"(r) : "f"(f));
    return __uint_as_float(r);
}

__device__ __forceinline__ void mma8(float* c, uint32_t a0, uint32_t a1, uint32_t a2, uint32_t a3,
                                     uint32_t b0, uint32_t b1)
{
    asm volatile("mma.sync.aligned.m16n8k8.row.col.f32.tf32.tf32.f32 "
                 "{%0,%1,%2,%3}, {%4,%5,%6,%7}, {%8,%9}, {%0,%1,%2,%3};"
                 : "+f"(c[0]), "+f"(c[1]), "+f"(c[2]), "+f"(c[3])
                 : "r"(a0), "r"(a1), "r"(a2), "r"(a3), "r"(b0), "r"(b1));
}

// 32x128 block tile, 8 warps (16 cols each). As pitch 36, Ws pitch 132. One K-chunk of 32.
__device__ __forceinline__ void mma_chunk(const float* As, const float* Ws,
                                          int n0w, int g, int tig, float acc[2][2][4])
{
    #pragma unroll
    for (int j=0;j<4;j++) {
        uint32_t a[2][4];
        #pragma unroll
        for (int mi=0;mi<2;mi++) {
            int rb = mi*16;
            a[mi][0] = __float_as_uint(As[(rb+g)*36   + j*8+tig]);
            a[mi][1] = __float_as_uint(As[(rb+g+8)*36 + j*8+tig]);
            a[mi][2] = __float_as_uint(As[(rb+g)*36   + j*8+tig+4]);
            a[mi][3] = __float_as_uint(As[(rb+g+8)*36 + j*8+tig+4]);
        }
        #pragma unroll
        for (int ni=0;ni<2;ni++) {
            int cb = n0w + ni*8 + g;
            uint32_t b0 = __float_as_uint(Ws[(j*8+tig)*132   + cb]);
            uint32_t b1 = __float_as_uint(Ws[(j*8+tig+4)*132 + cb]);
            mma8(acc[0][ni], a[0][0],a[0][1],a[0][2],a[0][3], b0,b1);
            mma8(acc[1][ni], a[1][0],a[1][1],a[1][2],a[1][3], b0,b1);
        }
    }
}

// A-frag chunk reading directly from pitch-132 smem (phase-2 of FFN), cols kc..kc+31
__device__ __forceinline__ void mma_chunk_F(const float* F, int kc, const float* Ws,
                                            int n0w, int g, int tig, float acc[2][2][4])
{
    #pragma unroll
    for (int j=0;j<4;j++) {
        uint32_t a[2][4];
        #pragma unroll
        for (int mi=0;mi<2;mi++) {
            int rb = mi*16;
            a[mi][0] = __float_as_uint(F[(rb+g)*132   + kc + j*8+tig]);
            a[mi][1] = __float_as_uint(F[(rb+g+8)*132 + kc + j*8+tig]);
            a[mi][2] = __float_as_uint(F[(rb+g)*132   + kc + j*8+tig+4]);
            a[mi][3] = __float_as_uint(F[(rb+g+8)*132 + kc + j*8+tig+4]);
        }
        #pragma unroll
        for (int ni=0;ni<2;ni++) {
            int cb = n0w + ni*8 + g;
            uint32_t b0 = __float_as_uint(Ws[(j*8+tig)*132   + cb]);
            uint32_t b1 = __float_as_uint(Ws[(j*8+tig+4)*132 + cb]);
            mma8(acc[0][ni], a[0][0],a[0][1],a[0][2],a[0][3], b0,b1);
            mma8(acc[1][ni], a[1][0],a[1][1],a[1][2],a[1][3], b0,b1);
        }
    }
}

// stage W chunk (32x128) into given Ws buffer (pitch 132), tf32-converted
__device__ __forceinline__ void stage_W(float* Ws, const float* W, int kc, int tid)
{
    #pragma unroll
    for (int u=0;u<4;u++) {
        int e = tid*16 + u*4;
        int r = e >> 7, c = e & 127;
        float4 w4 = *(const float4*)(W + (size_t)(kc + r)*128 + c);
        *(float4*)&Ws[r*132 + c] =
            make_float4(f2tf(w4.x), f2tf(w4.y), f2tf(w4.z), f2tf(w4.w));
    }
}

// ---------------- K/Q projections (tf32 mma, double-buffered) with inline embedding ----
__global__ void __launch_bounds__(256) kq_gemm_kernel(
    const float* __restrict__ ts,
    const float* __restrict__ w_per, const float* __restrict__ b_per,
    const float* __restrict__ w_lin, const float* __restrict__ b_lin,
    const float* __restrict__ Wq, const float* __restrict__ bq,
    const float* __restrict__ Wk, const float* __restrict__ bk)
{
    const int z = blockIdx.z;
    const float *W, *bias; float* C; int M;
    if (z == 0)      { W=Wk; bias=bk; C=g_Kb; M=NB*NL; }
    else if (z == 1) { W=Wq; bias=bq; C=g_Qb; M=NB*NL; }
    else             { W=Wq; bias=bq; C=g_Qc; M=128;  }
    const int m0 = blockIdx.x * 32;
    if (m0 >= M) return;

    __shared__ float As[2][32*36];
    __shared__ float Ws[2][32*132];

    const int tid = threadIdx.x;
    const int lane = tid & 31, warp = tid >> 5;
    const int g = lane >> 2, tig = lane & 3;
    const int n0w = warp * 16;

    float acc[2][2][4];
    #pragma unroll
    for (int a=0;a<2;a++)
        #pragma unroll
        for (int b=0;b<2;b++)
            #pragma unroll
            for (int c=0;c<4;c++) acc[a][b][c] = 0.f;

    const float wl = w_lin[0], bl = b_lin[0];
    const int ar = (tid*4) >> 5;
    const int ac = (tid*4) & 31;
    const int grow = m0 + ar;
    const float tval = (grow < M) ? ((z == 2) ? (float)grow*(1.0f/127.0f) : ts[grow]) : 0.f;

    auto stageA = [&](int kc, int bf) {
        float v[4];
        #pragma unroll
        for (int u=0;u<4;u++) {
            int j = kc + ac + u;
            v[u] = (j == 0) ? fmaf(tval, wl, bl)
                            : __sinf(fmaf(tval, w_per[j-1], b_per[j-1]));
        }
        *(float4*)&As[bf][ar*36 + ac] =
            make_float4(f2tf(v[0]), f2tf(v[1]), f2tf(v[2]), f2tf(v[3]));
    };

    stageA(0, 0);
    stage_W(Ws[0], W, 0, tid);
    __syncthreads();
    for (int c4=0;c4<4;c4++) {
        int cur = c4 & 1;
        if (c4 < 3) {
            stageA((c4+1)*32, cur^1);
            stage_W(Ws[cur^1], W, (c4+1)*32, tid);
        }
        mma_chunk(As[cur], Ws[cur], n0w, g, tig, acc);
        __syncthreads();
    }

    #pragma unroll
    for (int ni=0;ni<2;ni++) {
        int col = n0w + ni*8 + tig*2;
        float b0 = bias[col], b1v = bias[col+1];
        #pragma unroll
        for (int mi=0;mi<2;mi++) {
            int row = m0 + mi*16 + g;
            if (row < M)
                *(float2*)(C + (size_t)row*128 + col) =
                    make_float2(acc[mi][ni][0]+b0, acc[mi][ni][1]+b1v);
            if (row + 8 < M)
                *(float2*)(C + (size_t)(row+8)*128 + col) =
                    make_float2(acc[mi][ni][2]+b0, acc[mi][ni][3]+b1v);
        }
    }
}

// ---------------- QKV (tf32 mma, double-buffered) ----------------
__global__ void __launch_bounds__(256) qkv_gemm_kernel(
    const float* __restrict__ Wq, const float* __restrict__ bq,
    const float* __restrict__ Wk, const float* __restrict__ bk,
    const float* __restrict__ Wv, const float* __restrict__ bv)
{
    const float *W, *bias; float* C;
    if (blockIdx.z == 0)      { W=Wq; bias=bq; C=g_Q; }
    else if (blockIdx.z == 1) { W=Wk; bias=bk; C=g_K; }
    else                      { W=Wv; bias=bv; C=g_V; }
    const int m0 = blockIdx.x * 32;

    __shared__ float As[2][32*36];
    __shared__ float Ws[2][32*132];

    const int tid = threadIdx.x;
    const int lane = tid & 31, warp = tid >> 5;
    const int g = lane >> 2, tig = lane & 3;
    const int n0w = warp * 16;

    float acc[2][2][4];
    #pragma unroll
    for (int a=0;a<2;a++)
        #pragma unroll
        for (int b=0;b<2;b++)
            #pragma unroll
            for (int c=0;c<4;c++) acc[a][b][c] = 0.f;

    const int ar = (tid*4) >> 5;
    const int ac = (tid*4) & 31;
    const int grow = m0 + ar;

    auto stageA = [&](int kc, int bf) {
        float4 a4 = make_float4(0.f,0.f,0.f,0.f);
        if (grow < MTR) a4 = *(const float4*)(g_X + (size_t)grow*128 + kc + ac);
        *(float4*)&As[bf][ar*36 + ac] =
            make_float4(f2tf(a4.x), f2tf(a4.y), f2tf(a4.z), f2tf(a4.w));
    };

    stageA(0, 0);
    stage_W(Ws[0], W, 0, tid);
    __syncthreads();
    for (int c4=0;c4<4;c4++) {
        int cur = c4 & 1;
        if (c4 < 3) {
            stageA((c4+1)*32, cur^1);
            stage_W(Ws[cur^1], W, (c4+1)*32, tid);
        }
        mma_chunk(As[cur], Ws[cur], n0w, g, tig, acc);
        __syncthreads();
    }

    #pragma unroll
    for (int ni=0;ni<2;ni++) {
        int col = n0w + ni*8 + tig*2;
        float b0 = bias[col], b1v = bias[col+1];
        #pragma unroll
        for (int mi=0;mi<2;mi++) {
            int row = m0 + mi*16 + g;
            if (row < MTR)
                *(float2*)(C + (size_t)row*128 + col) =
                    make_float2(acc[mi][ni][0]+b0, acc[mi][ni][1]+b1v);
            if (row + 8 < MTR)
                *(float2*)(C + (size_t)(row+8)*128 + col) =
                    make_float2(acc[mi][ni][2]+b0, acc[mi][ni][3]+b1v);
        }
    }
}

// ---------------- masked per-channel attention (mTA), 2-key batched ----------------
__global__ void mta_kernel(const float* __restrict__ Qmain, const float* __restrict__ Qcls,
                           const float* __restrict__ K, const float* __restrict__ X,
                           float* __restrict__ o32main, float* __restrict__ o32cls)
{
    const int bh = blockIdx.y, b = bh >> 1, h = bh & 1;
    const bool cls = blockIdx.x >= 8;
    const int tile = cls ? (blockIdx.x - 8) : blockIdx.x;
    const float* Q = cls ? Qcls : Qmain;
    const int qStride = cls ? 0 : NL*128;
    const int Lq = cls ? 128 : NL;
    float* o32 = cls ? o32cls : o32main;

    const int tid = threadIdx.x, lane = tid & 31, warp = tid >> 5;
    const int qi = tile*64 + warp*16 + (lane & 15);
    const int half = lane >> 4;
    __shared__ float sK[2][2][16][64];
    __shared__ float sX[2][2][16][16];

    float4 qreg[16];
    const float* qp = Q + (size_t)b*qStride + (size_t)qi*128 + h*64;
    #pragma unroll
    for (int i=0;i<16;i++) qreg[i] = *(const float4*)(qp + i*4);

    float m = -1e30f;
    float den[8], num[8];
    #pragma unroll
    for (int c=0;c<8;c++){ den[c]=0.f; num[c]=0.f; }

    auto loadChunk = [&](int c, int bf) {
        #pragma unroll
        for (int u=0;u<4;u++) {
            int e = (tid*4+u)*4;
            int hh = e>>10, kk = (e>>6)&15, d = e&63;
            int kglob = hh*256 + c*16 + kk;
            *(float4*)&sK[bf][hh][kk][d] =
                *(const float4*)(K + ((size_t)b*NL + kglob)*128 + h*64 + d);
        }
        {
            int e = tid*4;
            int hh = e>>8, kk = (e>>4)&15, d = e&15;
            int kglob = hh*256 + c*16 + kk;
            *(float4*)&sX[bf][hh][kk][d] =
                *(const float4*)(X + ((size_t)b*NL + kglob)*16 + d);
        }
    };

    loadChunk(0, 0);
    __syncthreads();
    for (int c=0;c<16;c++) {
        const int cur = c & 1;
        if (c < 15) loadChunk(c+1, cur^1);
        #pragma unroll 2
        for (int kk=0;kk<16;kk+=2) {
            const float4* kr0 = (const float4*)sK[cur][half][kk];
            const float4* kr1 = (const float4*)sK[cur][half][kk+1];
            float4 A0 = make_float4(0.f,0.f,0.f,0.f);
            float4 A1 = make_float4(0.f,0.f,0.f,0.f);
            #pragma unroll
            for (int i=0;i<16;i++) {
                float4 k0 = kr0[i], k1 = kr1[i];
                float4 q = qreg[i];
                A0.x = fmaf(k0.x, q.x, A0.x); A1.x = fmaf(k1.x, q.x, A1.x);
                A0.y = fmaf(k0.y, q.y, A0.y); A1.y = fmaf(k1.y, q.y, A1.y);
                A0.z = fmaf(k0.z, q.z, A0.z); A1.z = fmaf(k1.z, q.z, A1.z);
                A0.w = fmaf(k0.w, q.w, A0.w); A1.w = fmaf(k1.w, q.w, A1.w);
            }
            float s0 = ((A0.x+A0.y)+(A0.z+A0.w))*0.125f;
            float s1 = ((A1.x+A1.y)+(A1.z+A1.w))*0.125f;
            float mx = fmaxf(m, fmaxf(s0, s1));
            if (mx > m) {
                float f = fexp(m - mx);
                #pragma unroll
                for (int cc=0;cc<8;cc++){ den[cc]*=f; num[cc]*=f; }
                m = mx;
            }
            float e0 = fexp(s0 - m), e1 = fexp(s1 - m);
            const float* x0 = sX[cur][half][kk];
            const float* x1 = sX[cur][half][kk+1];
            #pragma unroll
            for (int cc=0;cc<8;cc++) {
                float t0 = e0 * x0[8+cc];
                float t1 = e1 * x1[8+cc];
                den[cc] += t0 + t1;
                num[cc] = fmaf(t0, x0[cc], fmaf(t1, x1[cc], num[cc]));
            }
        }
        __syncthreads();
    }
    float m2 = __shfl_xor_sync(0xffffffffu, m, 16);
    float Mx = fmaxf(m, m2);
    float f1 = fexp(m - Mx), f2 = fexp(m2 - Mx);
    #pragma unroll
    for (int cc=0;cc<8;cc++) {
        float d2 = __shfl_xor_sync(0xffffffffu, den[cc], 16);
        float n2 = __shfl_xor_sync(0xffffffffu, num[cc], 16);
        den[cc] = den[cc]*f1 + d2*f2;
        num[cc] = num[cc]*f1 + n2*f2;
    }
    if (half == 0) {
        float res[16];
        #pragma unroll
        for (int cc=0;cc<8;cc++) {
            bool ok = den[cc] > 0.f;
            res[cc]   = ok ? num[cc]/den[cc] : 0.f;
            res[8+cc] = ok ? 1.f : 0.f;
        }
        float* dst = o32 + ((size_t)b*Lq + qi)*32 + h*16;
        #pragma unroll
        for (int i=0;i<4;i++)
            *(float4*)(dst + i*4) = make_float4(res[i*4],res[i*4+1],res[i*4+2],res[i*4+3]);
    }
}

// ---------------- 32->128 projection into merged X + cls-row fill ----------------
__global__ void proj32_kernel(const float* __restrict__ Am, const float* __restrict__ Ac,
                              const float* __restrict__ W, const float* __restrict__ bias,
                              const float* __restrict__ pos, const float* __restrict__ cls_emb)
{
    if (blockIdx.x == 320) {
        for (int i = threadIdx.x; i < 1024; i += 256) {
            int b = i >> 7, j = i & 127;
            float cv = cls_emb[j];
            g_X[((size_t)b*NT1)*128 + j] = cv;
            g_X[((size_t)M1R + (size_t)b*NT2)*128 + j] = cv + pos[j];
        }
        return;
    }
    __shared__ float sWT[128*36];
    __shared__ float sA[16*32];
    const bool cls = blockIdx.x >= 256;
    const float* A = cls ? Ac : Am;
    const int Lq = cls ? 128 : NL;
    const int r0 = (cls ? (blockIdx.x - 256) : blockIdx.x) * 16;
    for (int i = threadIdx.x; i < 4096; i += 256) {
        int r = i >> 7, c = i & 127;
        sWT[c*36 + r] = W[i];
    }
    for (int i = threadIdx.x; i < 512; i += 256)
        sA[i] = A[(size_t)(r0 + (i >> 5))*32 + (i & 31)];
    __syncthreads();
    #pragma unroll
    for (int u=0;u<8;u++) {
        int oi = threadIdx.x + u*256;
        int lr = oi >> 7, col = oi & 127;
        int r = r0 + lr;
        float acc = bias[col];
        const float4* wp = (const float4*)&sWT[col*36];
        const float4* ap = (const float4*)&sA[lr*32];
        #pragma unroll
        for (int k8=0;k8<8;k8++) {
            float4 w = wp[k8];
            float4 a = ap[k8];
            acc = fmaf(a.x, w.x, acc);
            acc = fmaf(a.y, w.y, acc);
            acc = fmaf(a.z, w.z, acc);
            acc = fmaf(a.w, w.w, acc);
        }
        int bb = r / Lq, q = r % Lq;
        size_t row;
        if (cls) row = (size_t)bb*NT1 + 1 + q;
        else   { row = (size_t)M1R + (size_t)bb*NT2 + 1 + q; acc += pos[(size_t)(1+q)*128 + col]; }
        g_X[row*128 + col] = acc;
    }
}

// ---------------- FUSED tblock attention (double-buffered, 2-key batched) + epilogue ----
__global__ void __launch_bounds__(256, 1) tattn_kernel(const float* __restrict__ tWo,
                                                       const float* __restrict__ tbo,
                                                       const float* __restrict__ lng,
                                                       const float* __restrict__ lnb)
{
    const int y = blockIdx.y;
    const int part = y >> 3;
    const int b = y & 7;
    const int T = part ? NT2 : NT1;
    const int base = part ? (M1R + b*NT2) : (b*NT1);
    if (blockIdx.x * 64 >= T) return;

    extern __shared__ float sm[];
    float* sK   = sm;                  // [buf][head][half][16][64] = 8192
    float* sV   = sm + 8192;
    float* sAOt = sm + 16384;          // [128][65]
    float* sWs  = sm + 16384 + 128*65; // [16][128]

    const int tid = threadIdx.x;
    const int head = tid >> 7;
    const int wt = tid & 127;
    const int lane = wt & 31, warp4 = wt >> 5;
    const int qi = blockIdx.x*64 + warp4*16 + (lane & 15);
    const int half = lane >> 4;

    float4 qreg[16];
    if (qi < T) {
        const float* qp = g_Q + ((size_t)base + qi)*128 + head*64;
        #pragma unroll
        for (int i=0;i<16;i++) qreg[i] = *(const float4*)(qp + i*4);
    } else {
        #pragma unroll
        for (int i=0;i<16;i++) qreg[i] = make_float4(0.f,0.f,0.f,0.f);
    }
    float m = -1e30f, l = 0.f;
    float o[64];
    #pragma unroll
    for (int d=0;d<64;d++) o[d]=0.f;

    const int half0 = (T + 1) >> 1;
    const int kbase = half ? half0 : 0;
    const int kend  = half ? T : half0;
    const int hl1 = T - half0;
    const int nch = (((half0 > hl1) ? half0 : hl1) + 15) >> 4;

    auto loadChunk = [&](int c, int bf) {
        #pragma unroll
        for (int u=0;u<8;u++) {
            int e = (tid*8 + u)*4;
            int isV = e >> 12;
            int r  = e & 4095;
            int hd = r >> 11, hh = (r >> 10) & 1, kk = (r >> 6) & 15, d = e & 63;
            int kglob = (hh ? half0 : 0) + c*16 + kk;
            int lim = hh ? T : half0;
            float4 v = make_float4(0.f,0.f,0.f,0.f);
            if (kglob < lim) {
                const float* src = (isV ? g_V : g_K) + ((size_t)base + kglob)*128 + hd*64 + d;
                v = *(const float4*)src;
            }
            float* dst = (isV ? sV : sK) + bf*4096 + hd*2048 + hh*1024 + kk*64 + d;
            *(float4*)dst = v;
        }
    };

    loadChunk(0, 0);
    __syncthreads();
    for (int c=0;c<nch;c++) {
        const int cur = c & 1;
        if (c+1 < nch) loadChunk(c+1, cur^1);
        const int k0 = kbase + c*16;
        const float* sKh = sK + cur*4096 + head*2048 + half*1024;
        const float* sVh = sV + cur*4096 + head*2048 + half*1024;
        #pragma unroll 2
        for (int kk=0;kk<16;kk+=2) {
            const float4* kr0 = (const float4*)(sKh + kk*64);
            const float4* kr1 = (const float4*)(sKh + (kk+1)*64);
            float4 A0 = make_float4(0.f,0.f,0.f,0.f);
            float4 A1 = make_float4(0.f,0.f,0.f,0.f);
            #pragma unroll
            for (int i=0;i<16;i++) {
                float4 k0v = kr0[i], k1v = kr1[i];
                float4 q = qreg[i];
                A0.x = fmaf(k0v.x, q.x, A0.x); A1.x = fmaf(k1v.x, q.x, A1.x);
                A0.y = fmaf(k0v.y, q.y, A0.y); A1.y = fmaf(k1v.y, q.y, A1.y);
                A0.z = fmaf(k0v.z, q.z, A0.z); A1.z = fmaf(k1v.z, q.z, A1.z);
                A0.w = fmaf(k0v.w, q.w, A0.w); A1.w = fmaf(k1v.w, q.w, A1.w);
            }
            float s0 = ((A0.x+A0.y)+(A0.z+A0.w))*0.125f;
            float s1 = ((A1.x+A1.y)+(A1.z+A1.w))*0.125f;
            bool v0 = (k0 + kk < kend), v1 = (k0 + kk + 1 < kend);
            float mx = m;
            if (v0) mx = fmaxf(mx, s0);
            if (v1) mx = fmaxf(mx, s1);
            if (mx > m) {
                float f = fexp(m - mx);
                l *= f;
                #pragma unroll
                for (int d=0;d<64;d++) o[d]*=f;
                m = mx;
            }
            float e0 = v0 ? fexp(s0 - m) : 0.f;
            float e1 = v1 ? fexp(s1 - m) : 0.f;
            l += e0 + e1;
            const float4* vr0 = (const float4*)(sVh + kk*64);
            const float4* vr1 = (const float4*)(sVh + (kk+1)*64);
            #pragma unroll
            for (int i=0;i<16;i++) {
                float4 w0 = vr0[i], w1 = vr1[i];
                o[i*4+0] = fmaf(e0, w0.x, fmaf(e1, w1.x, o[i*4+0]));
                o[i*4+1] = fmaf(e0, w0.y, fmaf(e1, w1.y, o[i*4+1]));
                o[i*4+2] = fmaf(e0, w0.z, fmaf(e1, w1.z, o[i*4+2]));
                o[i*4+3] = fmaf(e0, w0.w, fmaf(e1, w1.w, o[i*4+3]));
            }
        }
        __syncthreads();
    }
    float m2 = __shfl_xor_sync(0xffffffffu, m, 16);
    float Mx = fmaxf(m, m2);
    float f1 = fexp(m - Mx), f2 = fexp(m2 - Mx);
    float l2 = __shfl_xor_sync(0xffffffffu, l, 16);
    l = l*f1 + l2*f2;
    #pragma unroll
    for (int d=0;d<64;d++) {
        float o2 = __shfl_xor_sync(0xffffffffu, o[d], 16);
        o[d] = o[d]*f1 + o2*f2;
    }
    if (half == 0) {
        float inv = 1.0f / l;
        int qlocal = warp4*16 + (lane & 15);
        #pragma unroll
        for (int d=0;d<64;d++)
            sAOt[(head*64 + d)*65 + qlocal] = o[d]*inv;
    }
    __syncthreads();

    // ---- epilogue: AO(64x128) @ tWo + tbo + residual(g_X) → LN1 → g_X2 ----
    const int tn = tid & 31, tm = tid >> 5;
    float acc[8][4];
    #pragma unroll
    for (int i=0;i<8;i++)
        #pragma unroll
        for (int j=0;j<4;j++) acc[i][j] = 0.f;

    for (int kk = 0; kk < 128; kk += 16) {
        int e0 = tid*8, e1 = tid*8 + 4;
        float4 w0 = *(const float4*)(tWo + (size_t)(kk + (e0>>7))*128 + (e0&127));
        float4 w1 = *(const float4*)(tWo + (size_t)(kk + (e1>>7))*128 + (e1&127));
        __syncthreads();
        *(float4*)&sWs[e0] = w0;
        *(float4*)&sWs[e1] = w1;
        __syncthreads();
        #pragma unroll
        for (int k=0;k<16;k++) {
            float bv[4];
            *(float4*)bv = *(const float4*)&sWs[k*128 + tn*4];
            const float* ar = &sAOt[(kk+k)*65 + tm*8];
            #pragma unroll
            for (int i=0;i<8;i++) {
                float a = ar[i];
                #pragma unroll
                for (int j=0;j<4;j++) acc[i][j] = fmaf(a, bv[j], acc[i][j]);
            }
        }
    }

    float4 bo4 = *(const float4*)(tbo + tn*4);
    float bo[4] = {bo4.x, bo4.y, bo4.z, bo4.w};
    float4 g4 = *(const float4*)(lng + tn*4);
    float4 be4 = *(const float4*)(lnb + tn*4);
    float gg[4] = {g4.x, g4.y, g4.z, g4.w};
    float lb[4] = {be4.x, be4.y, be4.z, be4.w};

    #pragma unroll
    for (int i=0;i<8;i++) {
        int qrow = blockIdx.x*64 + tm*8 + i;
        if (qrow >= T) continue;
        size_t gr = (size_t)base + qrow;
        float4 rv = *(const float4*)(g_X + gr*128 + tn*4);
        float v[4];
        v[0] = acc[i][0] + bo[0] + rv.x;
        v[1] = acc[i][1] + bo[1] + rv.y;
        v[2] = acc[i][2] + bo[2] + rv.z;
        v[3] = acc[i][3] + bo[3] + rv.w;
        float s = v[0]+v[1]+v[2]+v[3];
        float s2 = v[0]*v[0]+v[1]*v[1]+v[2]*v[2]+v[3]*v[3];
        #pragma unroll
        for (int off=16; off>0; off>>=1) {
            s  += __shfl_xor_sync(0xffffffffu, s,  off);
            s2 += __shfl_xor_sync(0xffffffffu, s2, off);
        }
        float mean = s * (1.f/128.f);
        float var  = s2 * (1.f/128.f) - mean*mean;
        float rs   = rsqrtf(var + 1e-5f);
        float4 ov;
        ov.x = (v[0]-mean)*rs*gg[0] + lb[0];
        ov.y = (v[1]-mean)*rs*gg[1] + lb[1];
        ov.z = (v[2]-mean)*rs*gg[2] + lb[2];
        ov.w = (v[3]-mean)*rs*gg[3] + lb[3];
        *(float4*)(g_X2 + gr*128 + tn*4) = ov;
    }
}

// ---------------- FUSED FFN (tf32 mma, double-buffered) + LN2 + inline pooling ----------
// dyn smem: As 2*32*36 | Ws 2*32*132 | F 32*132
__global__ void __launch_bounds__(256, 1) ffn_kernel(
    const float* __restrict__ fW1, const float* __restrict__ fb1,
    const float* __restrict__ fW2, const float* __restrict__ fb2,
    const float* __restrict__ lng, const float* __restrict__ lnb,
    const float* __restrict__ pW, const float* __restrict__ pb,
    float* __restrict__ dpool, float* __restrict__ dlast)
{
    extern __shared__ float sm[];
    float* As = sm;                        // 2 x 32*36
    float* Ws = sm + 2*32*36;              // 2 x 32*132
    float* F  = sm + 2*32*36 + 2*32*132;   // 32*132

    const int m0 = blockIdx.x * 32;
    const int tid = threadIdx.x;
    const int lane = tid & 31, warp = tid >> 5;
    const int g = lane >> 2, tig = lane & 3;
    const int n0w = warp * 16;

    float acc[2][2][4];
    #pragma unroll
    for (int a=0;a<2;a++)
        #pragma unroll
        for (int b=0;b<2;b++)
            #pragma unroll
            for (int c=0;c<4;c++) acc[a][b][c] = 0.f;

    const int ar = (tid*4) >> 5;
    const int ac = (tid*4) & 31;
    const int grow = m0 + ar;

    auto stageA = [&](int kc, int bf) {
        float4 a4 = make_float4(0.f,0.f,0.f,0.f);
        if (grow < MTR) a4 = *(const float4*)(g_X2 + (size_t)grow*128 + kc + ac);
        *(float4*)&As[bf*32*36 + ar*36 + ac] =
            make_float4(f2tf(a4.x), f2tf(a4.y), f2tf(a4.z), f2tf(a4.w));
    };

    // phase 1: F = relu(X2 @ W1 + b1)
    stageA(0, 0);
    stage_W(Ws, fW1, 0, tid);
    __syncthreads();
    for (int c4=0;c4<4;c4++) {
        int cur = c4 & 1;
        if (c4 < 3) {
            stageA((c4+1)*32, cur^1);
            stage_W(Ws + (cur^1)*32*132, fW1, (c4+1)*32, tid);
        }
        mma_chunk(As + cur*32*36, Ws + cur*32*132, n0w, g, tig, acc);
        __syncthreads();
    }
    #pragma unroll
    for (int ni=0;ni<2;ni++) {
        int col = n0w + ni*8 + tig*2;
        float b0 = fb1[col], b1v = fb1[col+1];
        #pragma unroll
        for (int mi=0;mi<2;mi++) {
            int row = mi*16 + g;
            F[row*132 + col]       = f2tf(fmaxf(acc[mi][ni][0]+b0,  0.f));
            F[row*132 + col+1]     = f2tf(fmaxf(acc[mi][ni][1]+b1v, 0.f));
            F[(row+8)*132 + col]   = f2tf(fmaxf(acc[mi][ni][2]+b0,  0.f));
            F[(row+8)*132 + col+1] = f2tf(fmaxf(acc[mi][ni][3]+b1v, 0.f));
        }
    }

    // phase 2: out = F @ W2 (W double-buffered)
    #pragma unroll
    for (int a=0;a<2;a++)
        #pragma unroll
        for (int b=0;b<2;b++)
            #pragma unroll
            for (int c=0;c<4;c++) acc[a][b][c] = 0.f;

    stage_W(Ws, fW2, 0, tid);
    __syncthreads();
    for (int c4=0;c4<4;c4++) {
        int cur = c4 & 1;
        if (c4 < 3) stage_W(Ws + (cur^1)*32*132, fW2, (c4+1)*32, tid);
        mma_chunk_F(F, c4*32, Ws + cur*32*132, n0w, g, tig, acc);
        __syncthreads();
    }

    // stash phase-2 result (+b2) into F (fp32)
    #pragma unroll
    for (int ni=0;ni<2;ni++) {
        int col = n0w + ni*8 + tig*2;
        float b0 = fb2[col], b1v = fb2[col+1];
        #pragma unroll
        for (int mi=0;mi<2;mi++) {
            int row = mi*16 + g;
            F[row*132 + col]       = acc[mi][ni][0]+b0;
            F[row*132 + col+1]     = acc[mi][ni][1]+b1v;
            F[(row+8)*132 + col]   = acc[mi][ni][2]+b0;
            F[(row+8)*132 + col+1] = acc[mi][ni][3]+b1v;
        }
    }
    __syncthreads();

    // LN pass: warp w handles rows w*4 .. w*4+3
    float4 g4 = *(const float4*)(lng + lane*4);
    float4 be4 = *(const float4*)(lnb + lane*4);
    #pragma unroll
    for (int i=0;i<4;i++) {
        int row = warp*4 + i;
        int r = m0 + row;
        if (r >= MTR) continue;
        float4 fv = *(const float4*)&F[row*132 + lane*4];
        float4 rv = *(const float4*)(g_X2 + (size_t)r*128 + lane*4);
        float v[4] = {fv.x+rv.x, fv.y+rv.y, fv.z+rv.z, fv.w+rv.w};
        float s = v[0]+v[1]+v[2]+v[3];
        float s2 = v[0]*v[0]+v[1]*v[1]+v[2]*v[2]+v[3]*v[3];
        #pragma unroll
        for (int off=16; off>0; off>>=1) {
            s  += __shfl_xor_sync(0xffffffffu, s,  off);
            s2 += __shfl_xor_sync(0xffffffffu, s2, off);
        }
        float mean = s * (1.f/128.f);
        float var  = s2 * (1.f/128.f) - mean*mean;
        float rs   = rsqrtf(var + 1e-5f);
        float4 ov;
        ov.x = (v[0]-mean)*rs*g4.x + be4.x;
        ov.y = (v[1]-mean)*rs*g4.y + be4.y;
        ov.z = (v[2]-mean)*rs*g4.z + be4.z;
        ov.w = (v[3]-mean)*rs*g4.w + be4.w;
        if (r < M1R) {
            if (r % NT1 == 0) {
                int bidx = r / NT1;
                *(float4*)&As[lane*4] = ov;      // reuse As as row buffer
                __syncwarp();
                float4 accp = *(const float4*)(pb + lane*4);
                for (int k=0;k<128;k++) {
                    float sv = As[k];
                    float4 w = *(const float4*)(pW + (size_t)k*128 + lane*4);
                    accp.x = fmaf(sv, w.x, accp.x);
                    accp.y = fmaf(sv, w.y, accp.y);
                    accp.z = fmaf(sv, w.z, accp.z);
                    accp.w = fmaf(sv, w.w, accp.w);
                }
                float4 outv;
                outv.x = tanhf(accp.x); outv.y = tanhf(accp.y);
                outv.z = tanhf(accp.z); outv.w = tanhf(accp.w);
                *(float4*)(dpool + (size_t)bidx*128 + lane*4) = outv;
            }
        } else {
            int rr = r - M1R;
            int t  = rr % NT2;
            if (t == 0) continue;
            int b  = rr / NT2;
            *(float4*)(dlast + ((size_t)b*NL + t - 1)*128 + lane*4) = ov;
        }
    }
}

// ---------------- launch ----------------
extern "C" void kernel_launch(void* const* d_in, const int* in_sizes, int n_in,
                              void* d_out, int out_size)
{
    (void)in_sizes; (void)n_in; (void)out_size;
    const float* x       = (const float*)d_in[0];
    const float* ts      = (const float*)d_in[1];
    const float* w_per   = (const float*)d_in[2];
    const float* b_per   = (const float*)d_in[3];
    const float* w_lin   = (const float*)d_in[4];
    const float* b_lin   = (const float*)d_in[5];
    const float* Wq_t    = (const float*)d_in[6];
    const float* bq_t    = (const float*)d_in[7];
    const float* Wk_t    = (const float*)d_in[8];
    const float* bk_t    = (const float*)d_in[9];
    const float* Wo_t    = (const float*)d_in[10];
    const float* bo_t    = (const float*)d_in[11];
    const float* pos_emb = (const float*)d_in[12];
    const float* cls_emb = (const float*)d_in[13];
    const float* tWq = (const float*)d_in[14];
    const float* tbq = (const float*)d_in[15];
    const float* tWk = (const float*)d_in[16];
    const float* tbk = (const float*)d_in[17];
    const float* tWv = (const float*)d_in[18];
    const float* tbv = (const float*)d_in[19];
    const float* tWo = (const float*)d_in[20];
    const float* tbo = (const float*)d_in[21];
    const float* ln1_g = (const float*)d_in[22];
    const float* ln1_b = (const float*)d_in[23];
    const float* fW1 = (const float*)d_in[24];
    const float* fb1 = (const float*)d_in[25];
    const float* fW2 = (const float*)d_in[26];
    const float* fb2 = (const float*)d_in[27];
    const float* ln2_g = (const float*)d_in[28];
    const float* ln2_b = (const float*)d_in[29];
    const float* pW  = (const float*)d_in[30];
    const float* pb  = (const float*)d_in[31];
    float* dout = (float*)d_out;

    float *Qb, *Kb, *Qc, *o32a, *o32c;
    cudaGetSymbolAddress((void**)&Qb,   g_Qb);
    cudaGetSymbolAddress((void**)&Kb,   g_Kb);
    cudaGetSymbolAddress((void**)&Qc,   g_Qc);
    cudaGetSymbolAddress((void**)&o32a, g_o32a);
    cudaGetSymbolAddress((void**)&o32c, g_o32c);

    const int TATTN_SMEM = (8192 + 8192 + 128*65 + 2048) * 4;   // 107008 B
    cudaFuncSetAttribute(tattn_kernel, cudaFuncAttributeMaxDynamicSharedMemorySize, TATTN_SMEM);
    const int FFN_SMEM = (2*32*36 + 2*32*132 + 32*132) * 4;      // 59904 B
    cudaFuncSetAttribute(ffn_kernel, cudaFuncAttributeMaxDynamicSharedMemorySize, FFN_SMEM);

    // 1. K/Q projections with inline time-embedding (tf32 mma, double-buffered)
    kq_gemm_kernel<<<dim3(128, 1, 3), 256>>>(ts, w_per, b_per, w_lin, b_lin,
                                             Wq_t, bq_t, Wk_t, bk_t);

    // 2. masked channel attention (main + cls), double buffered, 2-key batched
    mta_kernel<<<dim3(10, NB*2), 128>>>(Qb, Qc, Kb, x, o32a, o32c);

    // 3. build merged tblock input (incl. cls rows)
    proj32_kernel<<<321, 256>>>(o32a, o32c, Wo_t, bo_t, pos_emb, cls_emb);

    // 4. QKV (tf32 mma, double-buffered)
    qkv_gemm_kernel<<<dim3((MTR+31)/32, 1, 3), 256>>>(tWq, tbq, tWk, tbk, tWv, tbv);

    // 5. fused attention (double buffered, 2-key batched) + Wo + residual + LN1 → X2
    tattn_kernel<<<dim3((NT2+63)/64, 16), 256, TATTN_SMEM>>>(tWo, tbo, ln1_g, ln1_b);

    // 6. fused FFN (tf32 mma, double-buffered) + residual + LN2 + inline cls pooling
    ffn_kernel<<<(MTR+31)/32, 256, FFN_SMEM>>>(fW1, fb1, fW2, fb2, ln2_g, ln2_b,
                                               pW, pb, dout, dout + 1024);
}

// round 14
// speedup vs baseline: 1.0859x; 1.0859x over previous
#include <cuda_runtime.h>
#include <math.h>
#include <stdint.h>

#define NB 8
#define NL 512
#define NE 128
#define NT1 129
#define NT2 513
#define M1R (NB*NT1)        // 1032
#define M2R (NB*NT2)        // 4104
#define MTR (M1R+M2R)       // 5136
#define ACH (32*36)         // one A chunk (32 rows x 32 cols, pitch 36)

// ---------------- device scratch ----------------
__device__ float g_Qb   [NB*NL*NE];
__device__ float g_Kb   [NB*NL*NE];
__device__ float g_Qc   [128*NE];
__device__ float g_o32a [NB*NL*32];
__device__ float g_o32c [NB*128*32];
__device__ float g_X    [MTR*128];
__device__ float g_Q    [MTR*128];
__device__ float g_K    [MTR*128];
__device__ float g_V    [MTR*128];
__device__ float g_X2   [MTR*128];

// ---------------- fast exp on FMA/ALU pipes (args <= 0) ----------------
__device__ __forceinline__ float fexp(float x)
{
    x = fmaxf(x, -80.0f);
    float t  = x * 1.4426950408889634f;
    float kf = t + 12582912.0f;
    int   k  = __float_as_int(kf) - 0x4B400000;
    float f  = t - (kf - 12582912.0f);
    float p  = 1.3333558e-3f;
    p = fmaf(p, f, 9.6181291e-3f);
    p = fmaf(p, f, 5.5504109e-2f);
    p = fmaf(p, f, 2.4022651e-1f);
    p = fmaf(p, f, 6.9314718e-1f);
    p = fmaf(p, f, 1.0f);
    return __int_as_float(__float_as_int(p) + (k << 23));
}

// ---------------- tf32 helpers ----------------
__device__ __forceinline__ float f2tf(float f)
{
    uint32_t r;
    asm("cvt.rna.tf32.f32 %0, %1;" : "=r"(r) : "f"(f));
    return __uint_as_float(r);
}

__device__ __forceinline__ void mma8(float* c, uint32_t a0, uint32_t a1, uint32_t a2, uint32_t a3,
                                     uint32_t b0, uint32_t b1)
{
    asm volatile("mma.sync.aligned.m16n8k8.row.col.f32.tf32.tf32.f32 "
                 "{%0,%1,%2,%3}, {%4,%5,%6,%7}, {%8,%9}, {%0,%1,%2,%3};"
                 : "+f"(c[0]), "+f"(c[1]), "+f"(c[2]), "+f"(c[3])
                 : "r"(a0), "r"(a1), "r"(a2), "r"(a3), "r"(b0), "r"(b1));
}

// 32x128 block tile, 8 warps (16 cols each). As pitch 36, Ws pitch 132. One K-chunk of 32.
__device__ __forceinline__ void mma_chunk(const float* As, const float* Ws,
                                          int n0w, int g, int tig, float acc[2][2][4])
{
    #pragma unroll
    for (int j=0;j<4;j++) {
        uint32_t a[2][4];
        #pragma unroll
        for (int mi=0;mi<2;mi++) {
            int rb = mi*16;
            a[mi][0] = __float_as_uint(As[(rb+g)*36   + j*8+tig]);
            a[mi][1] = __float_as_uint(As[(rb+g+8)*36 + j*8+tig]);
            a[mi][2] = __float_as_uint(As[(rb+g)*36   + j*8+tig+4]);
            a[mi][3] = __float_as_uint(As[(rb+g+8)*36 + j*8+tig+4]);
        }
        #pragma unroll
        for (int ni=0;ni<2;ni++) {
            int cb = n0w + ni*8 + g;
            uint32_t b0 = __float_as_uint(Ws[(j*8+tig)*132   + cb]);
            uint32_t b1 = __float_as_uint(Ws[(j*8+tig+4)*132 + cb]);
            mma8(acc[0][ni], a[0][0],a[0][1],a[0][2],a[0][3], b0,b1);
            mma8(acc[1][ni], a[1][0],a[1][1],a[1][2],a[1][3], b0,b1);
        }
    }
}

// A-frag chunk reading directly from pitch-132 smem (phase-2 of FFN), cols kc..kc+31
__device__ __forceinline__ void mma_chunk_F(const float* F, int kc, const float* Ws,
                                            int n0w, int g, int tig, float acc[2][2][4])
{
    #pragma unroll
    for (int j=0;j<4;j++) {
        uint32_t a[2][4];
        #pragma unroll
        for (int mi=0;mi<2;mi++) {
            int rb = mi*16;
            a[mi][0] = __float_as_uint(F[(rb+g)*132   + kc + j*8+tig]);
            a[mi][1] = __float_as_uint(F[(rb+g+8)*132 + kc + j*8+tig]);
            a[mi][2] = __float_as_uint(F[(rb+g)*132   + kc + j*8+tig+4]);
            a[mi][3] = __float_as_uint(F[(rb+g+8)*132 + kc + j*8+tig+4]);
        }
        #pragma unroll
        for (int ni=0;ni<2;ni++) {
            int cb = n0w + ni*8 + g;
            uint32_t b0 = __float_as_uint(Ws[(j*8+tig)*132   + cb]);
            uint32_t b1 = __float_as_uint(Ws[(j*8+tig+4)*132 + cb]);
            mma8(acc[0][ni], a[0][0],a[0][1],a[0][2],a[0][3], b0,b1);
            mma8(acc[1][ni], a[1][0],a[1][1],a[1][2],a[1][3], b0,b1);
        }
    }
}

// stage FULL W (128x128) into Ws (pitch 132), tf32-converted, coalesced
__device__ __forceinline__ void stage_Wfull(float* Ws, const float* W, int tid)
{
    #pragma unroll
    for (int u=0;u<16;u++) {
        int e = u*1024 + tid*4;
        int r = e >> 7, c = e & 127;
        float4 w4 = *(const float4*)(W + (size_t)r*128 + c);
        *(float4*)&Ws[r*132 + c] =
            make_float4(f2tf(w4.x), f2tf(w4.y), f2tf(w4.z), f2tf(w4.w));
    }
}

// ---------------- K/Q projections (tf32 mma, full staging) with inline embedding ----------
__global__ void __launch_bounds__(256) kq_gemm_kernel(
    const float* __restrict__ ts,
    const float* __restrict__ w_per, const float* __restrict__ b_per,
    const float* __restrict__ w_lin, const float* __restrict__ b_lin,
    const float* __restrict__ Wq, const float* __restrict__ bq,
    const float* __restrict__ Wk, const float* __restrict__ bk)
{
    const int z = blockIdx.z;
    const float *W, *bias; float* C; int M;
    if (z == 0)      { W=Wk; bias=bk; C=g_Kb; M=NB*NL; }
    else if (z == 1) { W=Wq; bias=bq; C=g_Qb; M=NB*NL; }
    else             { W=Wq; bias=bq; C=g_Qc; M=128;  }
    const int m0 = blockIdx.x * 32;
    if (m0 >= M) return;

    extern __shared__ float sm[];
    float* Ws = sm;             // 128*132
    float* As = sm + 128*132;   // 4 * ACH

    const int tid = threadIdx.x;
    const int lane = tid & 31, warp = tid >> 5;
    const int g = lane >> 2, tig = lane & 3;
    const int n0w = warp * 16;

    // ---- generate A (time embedding) : thread owns row tid>>3, cols (tid&7)*16 .. +15 ----
    {
        const float wl = w_lin[0], bl = b_lin[0];
        const int row = tid >> 3;
        const int col0 = (tid & 7) * 16;
        const int grow = m0 + row;
        const float tval = (grow < M) ? ((z == 2) ? (float)grow*(1.0f/127.0f) : ts[grow]) : 0.f;
        #pragma unroll
        for (int u4=0;u4<4;u4++) {
            int cb = col0 + u4*4;
            float v[4];
            #pragma unroll
            for (int u=0;u<4;u++) {
                int j = cb + u;
                v[u] = (j == 0) ? fmaf(tval, wl, bl)
                                : __sinf(fmaf(tval, w_per[j-1], b_per[j-1]));
            }
            int chunk = cb >> 5;
            *(float4*)&As[chunk*ACH + row*36 + (cb & 31)] =
                make_float4(f2tf(v[0]), f2tf(v[1]), f2tf(v[2]), f2tf(v[3]));
        }
    }
    stage_Wfull(Ws, W, tid);
    __syncthreads();

    float acc[2][2][4];
    #pragma unroll
    for (int a=0;a<2;a++)
        #pragma unroll
        for (int b=0;b<2;b++)
            #pragma unroll
            for (int c=0;c<4;c++) acc[a][b][c] = 0.f;

    #pragma unroll
    for (int c4=0;c4<4;c4++)
        mma_chunk(As + c4*ACH, Ws + c4*32*132, n0w, g, tig, acc);

    #pragma unroll
    for (int ni=0;ni<2;ni++) {
        int col = n0w + ni*8 + tig*2;
        float b0 = bias[col], b1v = bias[col+1];
        #pragma unroll
        for (int mi=0;mi<2;mi++) {
            int row = m0 + mi*16 + g;
            if (row < M)
                *(float2*)(C + (size_t)row*128 + col) =
                    make_float2(acc[mi][ni][0]+b0, acc[mi][ni][1]+b1v);
            if (row + 8 < M)
                *(float2*)(C + (size_t)(row+8)*128 + col) =
                    make_float2(acc[mi][ni][2]+b0, acc[mi][ni][3]+b1v);
        }
    }
}

// ---------------- QKV (tf32 mma, full staging) ----------------
__global__ void __launch_bounds__(256) qkv_gemm_kernel(
    const float* __restrict__ Wq, const float* __restrict__ bq,
    const float* __restrict__ Wk, const float* __restrict__ bk,
    const float* __restrict__ Wv, const float* __restrict__ bv)
{
    const float *W, *bias; float* C;
    if (blockIdx.z == 0)      { W=Wq; bias=bq; C=g_Q; }
    else if (blockIdx.z == 1) { W=Wk; bias=bk; C=g_K; }
    else                      { W=Wv; bias=bv; C=g_V; }
    const int m0 = blockIdx.x * 32;

    extern __shared__ float sm[];
    float* Ws = sm;             // 128*132
    float* As = sm + 128*132;   // 4 * ACH

    const int tid = threadIdx.x;
    const int lane = tid & 31, warp = tid >> 5;
    const int g = lane >> 2, tig = lane & 3;
    const int n0w = warp * 16;

    // stage all of A (32x128) from g_X, coalesced
    #pragma unroll
    for (int u=0;u<4;u++) {
        int e = u*1024 + tid*4;
        int row = e >> 7, col = e & 127;
        int grow = m0 + row;
        float4 a4 = make_float4(0.f,0.f,0.f,0.f);
        if (grow < MTR) a4 = *(const float4*)(g_X + (size_t)grow*128 + col);
        int chunk = col >> 5;
        *(float4*)&As[chunk*ACH + row*36 + (col & 31)] =
            make_float4(f2tf(a4.x), f2tf(a4.y), f2tf(a4.z), f2tf(a4.w));
    }
    stage_Wfull(Ws, W, tid);
    __syncthreads();

    float acc[2][2][4];
    #pragma unroll
    for (int a=0;a<2;a++)
        #pragma unroll
        for (int b=0;b<2;b++)
            #pragma unroll
            for (int c=0;c<4;c++) acc[a][b][c] = 0.f;

    #pragma unroll
    for (int c4=0;c4<4;c4++)
        mma_chunk(As + c4*ACH, Ws + c4*32*132, n0w, g, tig, acc);

    #pragma unroll
    for (int ni=0;ni<2;ni++) {
        int col = n0w + ni*8 + tig*2;
        float b0 = bias[col], b1v = bias[col+1];
        #pragma unroll
        for (int mi=0;mi<2;mi++) {
            int row = m0 + mi*16 + g;
            if (row < MTR)
                *(float2*)(C + (size_t)row*128 + col) =
                    make_float2(acc[mi][ni][0]+b0, acc[mi][ni][1]+b1v);
            if (row + 8 < MTR)
                *(float2*)(C + (size_t)(row+8)*128 + col) =
                    make_float2(acc[mi][ni][2]+b0, acc[mi][ni][3]+b1v);
        }
    }
}

// ---------------- masked per-channel attention (mTA), both heads per block ----------------
__global__ void __launch_bounds__(256, 1)
mta_kernel(const float* __restrict__ Qmain, const float* __restrict__ Qcls,
           const float* __restrict__ K, const float* __restrict__ X,
           float* __restrict__ o32main, float* __restrict__ o32cls)
{
    const int b = blockIdx.y;
    const bool cls = blockIdx.x >= 8;
    const int tile = cls ? (blockIdx.x - 8) : blockIdx.x;
    const float* Q = cls ? Qcls : Qmain;
    const int qStride = cls ? 0 : NL*128;
    const int Lq = cls ? 128 : NL;
    float* o32 = cls ? o32cls : o32main;

    const int tid = threadIdx.x;
    const int head = tid >> 7;
    const int wt = tid & 127;
    const int lane = wt & 31, warp = wt >> 5;
    const int qi = tile*64 + warp*16 + (lane & 15);
    const int half = lane >> 4;

    __shared__ float sK[2][2][2][16][64];   // buf, head, half, key, dim  (32 KB)
    __shared__ float sX[2][2][16][16];      // buf, half, key, ch         (8 KB)

    float4 qreg[16];
    const float* qp = Q + (size_t)b*qStride + (size_t)qi*128 + head*64;
    #pragma unroll
    for (int i=0;i<16;i++) qreg[i] = *(const float4*)(qp + i*4);

    float m = -1e30f;
    float den[8], num[8];
    #pragma unroll
    for (int c=0;c<8;c++){ den[c]=0.f; num[c]=0.f; }

    auto loadChunk = [&](int c, int bf) {
        #pragma unroll
        for (int u=0;u<4;u++) {
            int e = u*1024 + tid*4;              // 4096 floats: both heads
            int hd = e>>11, hh = (e>>10)&1, kk = (e>>6)&15, d = e&63;
            int kglob = hh*256 + c*16 + kk;
            *(float4*)&sK[bf][hd][hh][kk][d] =
                *(const float4*)(K + ((size_t)b*NL + kglob)*128 + hd*64 + d);
        }
        if (tid < 128) {
            int e = tid*4;                       // 512 floats (head-independent)
            int hh = e>>8, kk = (e>>4)&15, d = e&15;
            int kglob = hh*256 + c*16 + kk;
            *(float4*)&sX[bf][hh][kk][d] =
                *(const float4*)(X + ((size_t)b*NL + kglob)*16 + d);
        }
    };

    loadChunk(0, 0);
    __syncthreads();
    for (int c=0;c<16;c++) {
        const int cur = c & 1;
        if (c < 15) loadChunk(c+1, cur^1);
        #pragma unroll 2
        for (int kk=0;kk<16;kk+=2) {
            const float4* kr0 = (const float4*)sK[cur][head][half][kk];
            const float4* kr1 = (const float4*)sK[cur][head][half][kk+1];
            float4 A0 = make_float4(0.f,0.f,0.f,0.f);
            float4 A1 = make_float4(0.f,0.f,0.f,0.f);
            #pragma unroll
            for (int i=0;i<16;i++) {
                float4 k0 = kr0[i], k1 = kr1[i];
                float4 q = qreg[i];
                A0.x = fmaf(k0.x, q.x, A0.x); A1.x = fmaf(k1.x, q.x, A1.x);
                A0.y = fmaf(k0.y, q.y, A0.y); A1.y = fmaf(k1.y, q.y, A1.y);
                A0.z = fmaf(k0.z, q.z, A0.z); A1.z = fmaf(k1.z, q.z, A1.z);
                A0.w = fmaf(k0.w, q.w, A0.w); A1.w = fmaf(k1.w, q.w, A1.w);
            }
            float s0 = ((A0.x+A0.y)+(A0.z+A0.w))*0.125f;
            float s1 = ((A1.x+A1.y)+(A1.z+A1.w))*0.125f;
            float mx = fmaxf(m, fmaxf(s0, s1));
            if (mx > m) {
                float f = fexp(m - mx);
                #pragma unroll
                for (int cc=0;cc<8;cc++){ den[cc]*=f; num[cc]*=f; }
                m = mx;
            }
            float e0 = fexp(s0 - m), e1 = fexp(s1 - m);
            const float* x0 = sX[cur][half][kk];
            const float* x1 = sX[cur][half][kk+1];
            #pragma unroll
            for (int cc=0;cc<8;cc++) {
                float t0 = e0 * x0[8+cc];
                float t1 = e1 * x1[8+cc];
                den[cc] += t0 + t1;
                num[cc] = fmaf(t0, x0[cc], fmaf(t1, x1[cc], num[cc]));
            }
        }
        __syncthreads();
    }
    float m2 = __shfl_xor_sync(0xffffffffu, m, 16);
    float Mx = fmaxf(m, m2);
    float f1 = fexp(m - Mx), f2 = fexp(m2 - Mx);
    #pragma unroll
    for (int cc=0;cc<8;cc++) {
        float d2 = __shfl_xor_sync(0xffffffffu, den[cc], 16);
        float n2 = __shfl_xor_sync(0xffffffffu, num[cc], 16);
        den[cc] = den[cc]*f1 + d2*f2;
        num[cc] = num[cc]*f1 + n2*f2;
    }
    if (half == 0) {
        float res[16];
        #pragma unroll
        for (int cc=0;cc<8;cc++) {
            bool ok = den[cc] > 0.f;
            res[cc]   = ok ? num[cc]/den[cc] : 0.f;
            res[8+cc] = ok ? 1.f : 0.f;
        }
        float* dst = o32 + ((size_t)b*Lq + qi)*32 + head*16;
        #pragma unroll
        for (int i=0;i<4;i++)
            *(float4*)(dst + i*4) = make_float4(res[i*4],res[i*4+1],res[i*4+2],res[i*4+3]);
    }
}

// ---------------- 32->128 projection into merged X + cls-row fill ----------------
__global__ void proj32_kernel(const float* __restrict__ Am, const float* __restrict__ Ac,
                              const float* __restrict__ W, const float* __restrict__ bias,
                              const float* __restrict__ pos, const float* __restrict__ cls_emb)
{
    if (blockIdx.x == 320) {
        for (int i = threadIdx.x; i < 1024; i += 256) {
            int b = i >> 7, j = i & 127;
            float cv = cls_emb[j];
            g_X[((size_t)b*NT1)*128 + j] = cv;
            g_X[((size_t)M1R + (size_t)b*NT2)*128 + j] = cv + pos[j];
        }
        return;
    }
    __shared__ float sWT[128*36];
    __shared__ float sA[16*32];
    const bool cls = blockIdx.x >= 256;
    const float* A = cls ? Ac : Am;
    const int Lq = cls ? 128 : NL;
    const int r0 = (cls ? (blockIdx.x - 256) : blockIdx.x) * 16;
    for (int i = threadIdx.x; i < 4096; i += 256) {
        int r = i >> 7, c = i & 127;
        sWT[c*36 + r] = W[i];
    }
    for (int i = threadIdx.x; i < 512; i += 256)
        sA[i] = A[(size_t)(r0 + (i >> 5))*32 + (i & 31)];
    __syncthreads();
    #pragma unroll
    for (int u=0;u<8;u++) {
        int oi = threadIdx.x + u*256;
        int lr = oi >> 7, col = oi & 127;
        int r = r0 + lr;
        float acc = bias[col];
        const float4* wp = (const float4*)&sWT[col*36];
        const float4* ap = (const float4*)&sA[lr*32];
        #pragma unroll
        for (int k8=0;k8<8;k8++) {
            float4 w = wp[k8];
            float4 a = ap[k8];
            acc = fmaf(a.x, w.x, acc);
            acc = fmaf(a.y, w.y, acc);
            acc = fmaf(a.z, w.z, acc);
            acc = fmaf(a.w, w.w, acc);
        }
        int bb = r / Lq, q = r % Lq;
        size_t row;
        if (cls) row = (size_t)bb*NT1 + 1 + q;
        else   { row = (size_t)M1R + (size_t)bb*NT2 + 1 + q; acc += pos[(size_t)(1+q)*128 + col]; }
        g_X[row*128 + col] = acc;
    }
}

// ---------------- FUSED tblock attention (double-buffered, 2-key batched) + epilogue ----
__global__ void __launch_bounds__(256, 1) tattn_kernel(const float* __restrict__ tWo,
                                                       const float* __restrict__ tbo,
                                                       const float* __restrict__ lng,
                                                       const float* __restrict__ lnb)
{
    const int y = blockIdx.y;
    const int part = y >> 3;
    const int b = y & 7;
    const int T = part ? NT2 : NT1;
    const int base = part ? (M1R + b*NT2) : (b*NT1);
    if (blockIdx.x * 64 >= T) return;

    extern __shared__ float sm[];
    float* sK   = sm;                  // [buf][head][half][16][64] = 8192
    float* sV   = sm + 8192;
    float* sAOt = sm + 16384;          // [128][65]
    float* sWs  = sm + 16384 + 128*65; // [16][128]

    const int tid = threadIdx.x;
    const int head = tid >> 7;
    const int wt = tid & 127;
    const int lane = wt & 31, warp4 = wt >> 5;
    const int qi = blockIdx.x*64 + warp4*16 + (lane & 15);
    const int half = lane >> 4;

    float4 qreg[16];
    if (qi < T) {
        const float* qp = g_Q + ((size_t)base + qi)*128 + head*64;
        #pragma unroll
        for (int i=0;i<16;i++) qreg[i] = *(const float4*)(qp + i*4);
    } else {
        #pragma unroll
        for (int i=0;i<16;i++) qreg[i] = make_float4(0.f,0.f,0.f,0.f);
    }
    float m = -1e30f, l = 0.f;
    float o[64];
    #pragma unroll
    for (int d=0;d<64;d++) o[d]=0.f;

    const int half0 = (T + 1) >> 1;
    const int kbase = half ? half0 : 0;
    const int kend  = half ? T : half0;
    const int hl1 = T - half0;
    const int nch = (((half0 > hl1) ? half0 : hl1) + 15) >> 4;

    auto loadChunk = [&](int c, int bf) {
        #pragma unroll
        for (int u=0;u<8;u++) {
            int e = (tid*8 + u)*4;
            int isV = e >> 12;
            int r  = e & 4095;
            int hd = r >> 11, hh = (r >> 10) & 1, kk = (r >> 6) & 15, d = e & 63;
            int kglob = (hh ? half0 : 0) + c*16 + kk;
            int lim = hh ? T : half0;
            float4 v = make_float4(0.f,0.f,0.f,0.f);
            if (kglob < lim) {
                const float* src = (isV ? g_V : g_K) + ((size_t)base + kglob)*128 + hd*64 + d;
                v = *(const float4*)src;
            }
            float* dst = (isV ? sV : sK) + bf*4096 + hd*2048 + hh*1024 + kk*64 + d;
            *(float4*)dst = v;
        }
    };

    loadChunk(0, 0);
    __syncthreads();
    for (int c=0;c<nch;c++) {
        const int cur = c & 1;
        if (c+1 < nch) loadChunk(c+1, cur^1);
        const int k0 = kbase + c*16;
        const float* sKh = sK + cur*4096 + head*2048 + half*1024;
        const float* sVh = sV + cur*4096 + head*2048 + half*1024;
        #pragma unroll 2
        for (int kk=0;kk<16;kk+=2) {
            const float4* kr0 = (const float4*)(sKh + kk*64);
            const float4* kr1 = (const float4*)(sKh + (kk+1)*64);
            float4 A0 = make_float4(0.f,0.f,0.f,0.f);
            float4 A1 = make_float4(0.f,0.f,0.f,0.f);
            #pragma unroll
            for (int i=0;i<16;i++) {
                float4 k0v = kr0[i], k1v = kr1[i];
                float4 q = qreg[i];
                A0.x = fmaf(k0v.x, q.x, A0.x); A1.x = fmaf(k1v.x, q.x, A1.x);
                A0.y = fmaf(k0v.y, q.y, A0.y); A1.y = fmaf(k1v.y, q.y, A1.y);
                A0.z = fmaf(k0v.z, q.z, A0.z); A1.z = fmaf(k1v.z, q.z, A1.z);
                A0.w = fmaf(k0v.w, q.w, A0.w); A1.w = fmaf(k1v.w, q.w, A1.w);
            }
            float s0 = ((A0.x+A0.y)+(A0.z+A0.w))*0.125f;
            float s1 = ((A1.x+A1.y)+(A1.z+A1.w))*0.125f;
            bool v0 = (k0 + kk < kend), v1 = (k0 + kk + 1 < kend);
            float mx = m;
            if (v0) mx = fmaxf(mx, s0);
            if (v1) mx = fmaxf(mx, s1);
            if (mx > m) {
                float f = fexp(m - mx);
                l *= f;
                #pragma unroll
                for (int d=0;d<64;d++) o[d]*=f;
                m = mx;
            }
            float e0 = v0 ? fexp(s0 - m) : 0.f;
            float e1 = v1 ? fexp(s1 - m) : 0.f;
            l += e0 + e1;
            const float4* vr0 = (const float4*)(sVh + kk*64);
            const float4* vr1 = (const float4*)(sVh + (kk+1)*64);
            #pragma unroll
            for (int i=0;i<16;i++) {
                float4 w0 = vr0[i], w1 = vr1[i];
                o[i*4+0] = fmaf(e0, w0.x, fmaf(e1, w1.x, o[i*4+0]));
                o[i*4+1] = fmaf(e0, w0.y, fmaf(e1, w1.y, o[i*4+1]));
                o[i*4+2] = fmaf(e0, w0.z, fmaf(e1, w1.z, o[i*4+2]));
                o[i*4+3] = fmaf(e0, w0.w, fmaf(e1, w1.w, o[i*4+3]));
            }
        }
        __syncthreads();
    }
    float m2 = __shfl_xor_sync(0xffffffffu, m, 16);
    float Mx = fmaxf(m, m2);
    float f1 = fexp(m - Mx), f2 = fexp(m2 - Mx);
    float l2 = __shfl_xor_sync(0xffffffffu, l, 16);
    l = l*f1 + l2*f2;
    #pragma unroll
    for (int d=0;d<64;d++) {
        float o2 = __shfl_xor_sync(0xffffffffu, o[d], 16);
        o[d] = o[d]*f1 + o2*f2;
    }
    if (half == 0) {
        float inv = 1.0f / l;
        int qlocal = warp4*16 + (lane & 15);
        #pragma unroll
        for (int d=0;d<64;d++)
            sAOt[(head*64 + d)*65 + qlocal] = o[d]*inv;
    }
    __syncthreads();

    // ---- epilogue: AO(64x128) @ tWo + tbo + residual(g_X) → LN1 → g_X2 ----
    const int tn = tid & 31, tm = tid >> 5;
    float acc[8][4];
    #pragma unroll
    for (int i=0;i<8;i++)
        #pragma unroll
        for (int j=0;j<4;j++) acc[i][j] = 0.f;

    for (int kk = 0; kk < 128; kk += 16) {
        int e0 = tid*8, e1 = tid*8 + 4;
        float4 w0 = *(const float4*)(tWo + (size_t)(kk + (e0>>7))*128 + (e0&127));
        float4 w1 = *(const float4*)(tWo + (size_t)(kk + (e1>>7))*128 + (e1&127));
        __syncthreads();
        *(float4*)&sWs[e0] = w0;
        *(float4*)&sWs[e1] = w1;
        __syncthreads();
        #pragma unroll
        for (int k=0;k<16;k++) {
            float bv[4];
            *(float4*)bv = *(const float4*)&sWs[k*128 + tn*4];
            const float* ar = &sAOt[(kk+k)*65 + tm*8];
            #pragma unroll
            for (int i=0;i<8;i++) {
                float a = ar[i];
                #pragma unroll
                for (int j=0;j<4;j++) acc[i][j] = fmaf(a, bv[j], acc[i][j]);
            }
        }
    }

    float4 bo4 = *(const float4*)(tbo + tn*4);
    float bo[4] = {bo4.x, bo4.y, bo4.z, bo4.w};
    float4 g4 = *(const float4*)(lng + tn*4);
    float4 be4 = *(const float4*)(lnb + tn*4);
    float gg[4] = {g4.x, g4.y, g4.z, g4.w};
    float lb[4] = {be4.x, be4.y, be4.z, be4.w};

    #pragma unroll
    for (int i=0;i<8;i++) {
        int qrow = blockIdx.x*64 + tm*8 + i;
        if (qrow >= T) continue;
        size_t gr = (size_t)base + qrow;
        float4 rv = *(const float4*)(g_X + gr*128 + tn*4);
        float v[4];
        v[0] = acc[i][0] + bo[0] + rv.x;
        v[1] = acc[i][1] + bo[1] + rv.y;
        v[2] = acc[i][2] + bo[2] + rv.z;
        v[3] = acc[i][3] + bo[3] + rv.w;
        float s = v[0]+v[1]+v[2]+v[3];
        float s2 = v[0]*v[0]+v[1]*v[1]+v[2]*v[2]+v[3]*v[3];
        #pragma unroll
        for (int off=16; off>0; off>>=1) {
            s  += __shfl_xor_sync(0xffffffffu, s,  off);
            s2 += __shfl_xor_sync(0xffffffffu, s2, off);
        }
        float mean = s * (1.f/128.f);
        float var  = s2 * (1.f/128.f) - mean*mean;
        float rs   = rsqrtf(var + 1e-5f);
        float4 ov;
        ov.x = (v[0]-mean)*rs*gg[0] + lb[0];
        ov.y = (v[1]-mean)*rs*gg[1] + lb[1];
        ov.z = (v[2]-mean)*rs*gg[2] + lb[2];
        ov.w = (v[3]-mean)*rs*gg[3] + lb[3];
        *(float4*)(g_X2 + gr*128 + tn*4) = ov;
    }
}

// ---------------- FUSED FFN (tf32 mma, full staging) + LN2 + inline pooling ----------
// dyn smem: Ws 128*132 | As 4*ACH | F 32*132
__global__ void __launch_bounds__(256, 1) ffn_kernel(
    const float* __restrict__ fW1, const float* __restrict__ fb1,
    const float* __restrict__ fW2, const float* __restrict__ fb2,
    const float* __restrict__ lng, const float* __restrict__ lnb,
    const float* __restrict__ pW, const float* __restrict__ pb,
    float* __restrict__ dpool, float* __restrict__ dlast)
{
    extern __shared__ float sm[];
    float* Ws = sm;                         // 128*132
    float* As = sm + 128*132;               // 4*ACH
    float* F  = sm + 128*132 + 4*ACH;       // 32*132

    const int m0 = blockIdx.x * 32;
    const int tid = threadIdx.x;
    const int lane = tid & 31, warp = tid >> 5;
    const int g = lane >> 2, tig = lane & 3;
    const int n0w = warp * 16;

    float acc[2][2][4];
    #pragma unroll
    for (int a=0;a<2;a++)
        #pragma unroll
        for (int b=0;b<2;b++)
            #pragma unroll
            for (int c=0;c<4;c++) acc[a][b][c] = 0.f;

    // stage full A from g_X2 + full W1, one sync
    #pragma unroll
    for (int u=0;u<4;u++) {
        int e = u*1024 + tid*4;
        int row = e >> 7, col = e & 127;
        int grow = m0 + row;
        float4 a4 = make_float4(0.f,0.f,0.f,0.f);
        if (grow < MTR) a4 = *(const float4*)(g_X2 + (size_t)grow*128 + col);
        int chunk = col >> 5;
        *(float4*)&As[chunk*ACH + row*36 + (col & 31)] =
            make_float4(f2tf(a4.x), f2tf(a4.y), f2tf(a4.z), f2tf(a4.w));
    }
    stage_Wfull(Ws, fW1, tid);
    __syncthreads();

    #pragma unroll
    for (int c4=0;c4<4;c4++)
        mma_chunk(As + c4*ACH, Ws + c4*32*132, n0w, g, tig, acc);
    __syncthreads();     // all phase-1 reads of Ws done before overwrite

    // write F (relu, tf32) + stage full W2
    #pragma unroll
    for (int ni=0;ni<2;ni++) {
        int col = n0w + ni*8 + tig*2;
        float b0 = fb1[col], b1v = fb1[col+1];
        #pragma unroll
        for (int mi=0;mi<2;mi++) {
            int row = mi*16 + g;
            F[row*132 + col]       = f2tf(fmaxf(acc[mi][ni][0]+b0,  0.f));
            F[row*132 + col+1]     = f2tf(fmaxf(acc[mi][ni][1]+b1v, 0.f));
            F[(row+8)*132 + col]   = f2tf(fmaxf(acc[mi][ni][2]+b0,  0.f));
            F[(row+8)*132 + col+1] = f2tf(fmaxf(acc[mi][ni][3]+b1v, 0.f));
        }
    }
    stage_Wfull(Ws, fW2, tid);
    __syncthreads();

    // phase 2: out = F @ W2
    #pragma unroll
    for (int a=0;a<2;a++)
        #pragma unroll
        for (int b=0;b<2;b++)
            #pragma unroll
            for (int c=0;c<4;c++) acc[a][b][c] = 0.f;

    #pragma unroll
    for (int c4=0;c4<4;c4++)
        mma_chunk_F(F, c4*32, Ws + c4*32*132, n0w, g, tig, acc);
    __syncthreads();

    // stash phase-2 result (+b2) into F (fp32)
    #pragma unroll
    for (int ni=0;ni<2;ni++) {
        int col = n0w + ni*8 + tig*2;
        float b0 = fb2[col], b1v = fb2[col+1];
        #pragma unroll
        for (int mi=0;mi<2;mi++) {
            int row = mi*16 + g;
            F[row*132 + col]       = acc[mi][ni][0]+b0;
            F[row*132 + col+1]     = acc[mi][ni][1]+b1v;
            F[(row+8)*132 + col]   = acc[mi][ni][2]+b0;
            F[(row+8)*132 + col+1] = acc[mi][ni][3]+b1v;
        }
    }
    __syncthreads();

    // LN pass: warp w handles rows w*4 .. w*4+3
    float4 g4 = *(const float4*)(lng + lane*4);
    float4 be4 = *(const float4*)(lnb + lane*4);
    #pragma unroll
    for (int i=0;i<4;i++) {
        int row = warp*4 + i;
        int r = m0 + row;
        if (r >= MTR) continue;
        float4 fv = *(const float4*)&F[row*132 + lane*4];
        float4 rv = *(const float4*)(g_X2 + (size_t)r*128 + lane*4);
        float v[4] = {fv.x+rv.x, fv.y+rv.y, fv.z+rv.z, fv.w+rv.w};
        float s = v[0]+v[1]+v[2]+v[3];
        float s2 = v[0]*v[0]+v[1]*v[1]+v[2]*v[2]+v[3]*v[3];
        #pragma unroll
        for (int off=16; off>0; off>>=1) {
            s  += __shfl_xor_sync(0xffffffffu, s,  off);
            s2 += __shfl_xor_sync(0xffffffffu, s2, off);
        }
        float mean = s * (1.f/128.f);
        float var  = s2 * (1.f/128.f) - mean*mean;
        float rs   = rsqrtf(var + 1e-5f);
        float4 ov;
        ov.x = (v[0]-mean)*rs*g4.x + be4.x;
        ov.y = (v[1]-mean)*rs*g4.y + be4.y;
        ov.z = (v[2]-mean)*rs*g4.z + be4.z;
        ov.w = (v[3]-mean)*rs*g4.w + be4.w;
        if (r < M1R) {
            if (r % NT1 == 0) {
                int bidx = r / NT1;
                *(float4*)&As[lane*4] = ov;      // reuse As as row buffer
                __syncwarp();
                float4 accp = *(const float4*)(pb + lane*4);
                for (int k=0;k<128;k++) {
                    float sv = As[k];
                    float4 w = *(const float4*)(pW + (size_t)k*128 + lane*4);
                    accp.x = fmaf(sv, w.x, accp.x);
                    accp.y = fmaf(sv, w.y, accp.y);
                    accp.z = fmaf(sv, w.z, accp.z);
                    accp.w = fmaf(sv, w.w, accp.w);
                }
                float4 outv;
                outv.x = tanhf(accp.x); outv.y = tanhf(accp.y);
                outv.z = tanhf(accp.z); outv.w = tanhf(accp.w);
                *(float4*)(dpool + (size_t)bidx*128 + lane*4) = outv;
            }
        } else {
            int rr = r - M1R;
            int t  = rr % NT2;
            if (t == 0) continue;
            int b  = rr / NT2;
            *(float4*)(dlast + ((size_t)b*NL + t - 1)*128 + lane*4) = ov;
        }
    }
}

// ---------------- launch ----------------
extern "C" void kernel_launch(void* const* d_in, const int* in_sizes, int n_in,
                              void* d_out, int out_size)
{
    (void)in_sizes; (void)n_in; (void)out_size;
    const float* x       = (const float*)d_in[0];
    const float* ts      = (const float*)d_in[1];
    const float* w_per   = (const float*)d_in[2];
    const float* b_per   = (const float*)d_in[3];
    const float* w_lin   = (const float*)d_in[4];
    const float* b_lin   = (const float*)d_in[5];
    const float* Wq_t    = (const float*)d_in[6];
    const float* bq_t    = (const float*)d_in[7];
    const float* Wk_t    = (const float*)d_in[8];
    const float* bk_t    = (const float*)d_in[9];
    const float* Wo_t    = (const float*)d_in[10];
    const float* bo_t    = (const float*)d_in[11];
    const float* pos_emb = (const float*)d_in[12];
    const float* cls_emb = (const float*)d_in[13];
    const float* tWq = (const float*)d_in[14];
    const float* tbq = (const float*)d_in[15];
    const float* tWk = (const float*)d_in[16];
    const float* tbk = (const float*)d_in[17];
    const float* tWv = (const float*)d_in[18];
    const float* tbv = (const float*)d_in[19];
    const float* tWo = (const float*)d_in[20];
    const float* tbo = (const float*)d_in[21];
    const float* ln1_g = (const float*)d_in[22];
    const float* ln1_b = (const float*)d_in[23];
    const float* fW1 = (const float*)d_in[24];
    const float* fb1 = (const float*)d_in[25];
    const float* fW2 = (const float*)d_in[26];
    const float* fb2 = (const float*)d_in[27];
    const float* ln2_g = (const float*)d_in[28];
    const float* ln2_b = (const float*)d_in[29];
    const float* pW  = (const float*)d_in[30];
    const float* pb  = (const float*)d_in[31];
    float* dout = (float*)d_out;

    float *Qb, *Kb, *Qc, *o32a, *o32c;
    cudaGetSymbolAddress((void**)&Qb,   g_Qb);
    cudaGetSymbolAddress((void**)&Kb,   g_Kb);
    cudaGetSymbolAddress((void**)&Qc,   g_Qc);
    cudaGetSymbolAddress((void**)&o32a, g_o32a);
    cudaGetSymbolAddress((void**)&o32c, g_o32c);

    const int GEMM_SMEM = (128*132 + 4*ACH) * 4;                 // 86016 B
    cudaFuncSetAttribute(kq_gemm_kernel,  cudaFuncAttributeMaxDynamicSharedMemorySize, GEMM_SMEM);
    cudaFuncSetAttribute(qkv_gemm_kernel, cudaFuncAttributeMaxDynamicSharedMemorySize, GEMM_SMEM);
    const int TATTN_SMEM = (8192 + 8192 + 128*65 + 2048) * 4;    // 107008 B
    cudaFuncSetAttribute(tattn_kernel, cudaFuncAttributeMaxDynamicSharedMemorySize, TATTN_SMEM);
    const int FFN_SMEM = (128*132 + 4*ACH + 32*132) * 4;         // 102912 B
    cudaFuncSetAttribute(ffn_kernel, cudaFuncAttributeMaxDynamicSharedMemorySize, FFN_SMEM);

    // 1. K/Q projections with inline time-embedding
    kq_gemm_kernel<<<dim3(128, 1, 3), 256, GEMM_SMEM>>>(ts, w_per, b_per, w_lin, b_lin,
                                                        Wq_t, bq_t, Wk_t, bk_t);

    // 2. masked channel attention (both heads per block)
    mta_kernel<<<dim3(10, NB), 256>>>(Qb, Qc, Kb, x, o32a, o32c);

    // 3. build merged tblock input (incl. cls rows)
    proj32_kernel<<<321, 256>>>(o32a, o32c, Wo_t, bo_t, pos_emb, cls_emb);

    // 4. QKV
    qkv_gemm_kernel<<<dim3((MTR+31)/32, 1, 3), 256, GEMM_SMEM>>>(tWq, tbq, tWk, tbk, tWv, tbv);

    // 5. fused attention + Wo + residual + LN1 → X2
    tattn_kernel<<<dim3((NT2+63)/64, 16), 256, TATTN_SMEM>>>(tWo, tbo, ln1_g, ln1_b);

    // 6. fused FFN + residual + LN2 + inline cls pooling
    ffn_kernel<<<(MTR+31)/32, 256, FFN_SMEM>>>(fW1, fb1, fW2, fb2, ln2_g, ln2_b,
                                               pW, pb, dout, dout + 1024);
}

// round 16
// speedup vs baseline: 1.1999x; 1.1050x over previous
#include <cuda_runtime.h>
#include <math.h>
#include <stdint.h>

#define NB 8
#define NL 512
#define NE 128
#define NT1 129
#define NT2 513
#define M1R (NB*NT1)        // 1032
#define M2R (NB*NT2)        // 4104
#define MTR (M1R+M2R)       // 5136
#define ACH (32*36)         // one A chunk (32 rows x 32 cols, pitch 36)
#define SEGL 129            // key segment length
#define PREC 68             // g_part record: [m, l, pad, pad, o[64]] (16B-aligned)

// ---------------- device scratch ----------------
__device__ float g_Qb   [NB*NL*NE];
__device__ float g_Kb   [NB*NL*NE];
__device__ float g_Qc   [128*NE];
__device__ float g_o32a [NB*NL*32];
__device__ float g_o32c [NB*128*32];
__device__ float g_X    [MTR*128];
__device__ float g_Q    [MTR*128];
__device__ float g_K    [MTR*128];
__device__ float g_V    [MTR*128];
__device__ float g_X2   [MTR*128];
__device__ float g_part [MTR*2*4*PREC];   // (row, head, seg) records

// ---------------- fast exp on FMA/ALU pipes (args <= 0) ----------------
__device__ __forceinline__ float fexp(float x)
{
    x = fmaxf(x, -80.0f);
    float t  = x * 1.4426950408889634f;
    float kf = t + 12582912.0f;
    int   k  = __float_as_int(kf) - 0x4B400000;
    float f  = t - (kf - 12582912.0f);
    float p  = 1.3333558e-3f;
    p = fmaf(p, f, 9.6181291e-3f);
    p = fmaf(p, f, 5.5504109e-2f);
    p = fmaf(p, f, 2.4022651e-1f);
    p = fmaf(p, f, 6.9314718e-1f);
    p = fmaf(p, f, 1.0f);
    return __int_as_float(__float_as_int(p) + (k << 23));
}

// ---------------- tf32 helpers ----------------
__device__ __forceinline__ float f2tf(float f)
{
    uint32_t r;
    asm("cvt.rna.tf32.f32 %0, %1;" : "=r"(r) : "f"(f));
    return __uint_as_float(r);
}

__device__ __forceinline__ void mma8(float* c, uint32_t a0, uint32_t a1, uint32_t a2, uint32_t a3,
                                     uint32_t b0, uint32_t b1)
{
    asm volatile("mma.sync.aligned.m16n8k8.row.col.f32.tf32.tf32.f32 "
                 "{%0,%1,%2,%3}, {%4,%5,%6,%7}, {%8,%9}, {%0,%1,%2,%3};"
                 : "+f"(c[0]), "+f"(c[1]), "+f"(c[2]), "+f"(c[3])
                 : "r"(a0), "r"(a1), "r"(a2), "r"(a3), "r"(b0), "r"(b1));
}

__device__ __forceinline__ void mma_chunk(const float* As, const float* Ws,
                                          int n0w, int g, int tig, float acc[2][2][4])
{
    #pragma unroll
    for (int j=0;j<4;j++) {
        uint32_t a[2][4];
        #pragma unroll
        for (int mi=0;mi<2;mi++) {
            int rb = mi*16;
            a[mi][0] = __float_as_uint(As[(rb+g)*36   + j*8+tig]);
            a[mi][1] = __float_as_uint(As[(rb+g+8)*36 + j*8+tig]);
            a[mi][2] = __float_as_uint(As[(rb+g)*36   + j*8+tig+4]);
            a[mi][3] = __float_as_uint(As[(rb+g+8)*36 + j*8+tig+4]);
        }
        #pragma unroll
        for (int ni=0;ni<2;ni++) {
            int cb = n0w + ni*8 + g;
            uint32_t b0 = __float_as_uint(Ws[(j*8+tig)*132   + cb]);
            uint32_t b1 = __float_as_uint(Ws[(j*8+tig+4)*132 + cb]);
            mma8(acc[0][ni], a[0][0],a[0][1],a[0][2],a[0][3], b0,b1);
            mma8(acc[1][ni], a[1][0],a[1][1],a[1][2],a[1][3], b0,b1);
        }
    }
}

__device__ __forceinline__ void mma_chunk_F(const float* F, int kc, const float* Ws,
                                            int n0w, int g, int tig, float acc[2][2][4])
{
    #pragma unroll
    for (int j=0;j<4;j++) {
        uint32_t a[2][4];
        #pragma unroll
        for (int mi=0;mi<2;mi++) {
            int rb = mi*16;
            a[mi][0] = __float_as_uint(F[(rb+g)*132   + kc + j*8+tig]);
            a[mi][1] = __float_as_uint(F[(rb+g+8)*132 + kc + j*8+tig]);
            a[mi][2] = __float_as_uint(F[(rb+g)*132   + kc + j*8+tig+4]);
            a[mi][3] = __float_as_uint(F[(rb+g+8)*132 + kc + j*8+tig+4]);
        }
        #pragma unroll
        for (int ni=0;ni<2;ni++) {
            int cb = n0w + ni*8 + g;
            uint32_t b0 = __float_as_uint(Ws[(j*8+tig)*132   + cb]);
            uint32_t b1 = __float_as_uint(Ws[(j*8+tig+4)*132 + cb]);
            mma8(acc[0][ni], a[0][0],a[0][1],a[0][2],a[0][3], b0,b1);
            mma8(acc[1][ni], a[1][0],a[1][1],a[1][2],a[1][3], b0,b1);
        }
    }
}

__device__ __forceinline__ void stage_Wfull(float* Ws, const float* W, int tid)
{
    #pragma unroll
    for (int u=0;u<16;u++) {
        int e = u*1024 + tid*4;
        int r = e >> 7, c = e & 127;
        float4 w4 = *(const float4*)(W + (size_t)r*128 + c);
        *(float4*)&Ws[r*132 + c] =
            make_float4(f2tf(w4.x), f2tf(w4.y), f2tf(w4.z), f2tf(w4.w));
    }
}

// ---------------- K/Q projections with inline time-embedding ----------
__global__ void __launch_bounds__(256) kq_gemm_kernel(
    const float* __restrict__ ts,
    const float* __restrict__ w_per, const float* __restrict__ b_per,
    const float* __restrict__ w_lin, const float* __restrict__ b_lin,
    const float* __restrict__ Wq, const float* __restrict__ bq,
    const float* __restrict__ Wk, const float* __restrict__ bk)
{
    const int z = blockIdx.z;
    const float *W, *bias; float* C; int M;
    if (z == 0)      { W=Wk; bias=bk; C=g_Kb; M=NB*NL; }
    else if (z == 1) { W=Wq; bias=bq; C=g_Qb; M=NB*NL; }
    else             { W=Wq; bias=bq; C=g_Qc; M=128;  }
    const int m0 = blockIdx.x * 32;
    if (m0 >= M) return;

    extern __shared__ float sm[];
    float* Ws = sm;
    float* As = sm + 128*132;

    const int tid = threadIdx.x;
    const int lane = tid & 31, warp = tid >> 5;
    const int g = lane >> 2, tig = lane & 3;
    const int n0w = warp * 16;

    {
        const float wl = w_lin[0], bl = b_lin[0];
        const int row = tid >> 3;
        const int col0 = (tid & 7) * 16;
        const int grow = m0 + row;
        const float tval = (grow < M) ? ((z == 2) ? (float)grow*(1.0f/127.0f) : ts[grow]) : 0.f;
        #pragma unroll
        for (int u4=0;u4<4;u4++) {
            int cb = col0 + u4*4;
            float v[4];
            #pragma unroll
            for (int u=0;u<4;u++) {
                int j = cb + u;
                v[u] = (j == 0) ? fmaf(tval, wl, bl)
                                : __sinf(fmaf(tval, w_per[j-1], b_per[j-1]));
            }
            int chunk = cb >> 5;
            *(float4*)&As[chunk*ACH + row*36 + (cb & 31)] =
                make_float4(f2tf(v[0]), f2tf(v[1]), f2tf(v[2]), f2tf(v[3]));
        }
    }
    stage_Wfull(Ws, W, tid);
    __syncthreads();

    float acc[2][2][4];
    #pragma unroll
    for (int a=0;a<2;a++)
        #pragma unroll
        for (int b=0;b<2;b++)
            #pragma unroll
            for (int c=0;c<4;c++) acc[a][b][c] = 0.f;

    #pragma unroll
    for (int c4=0;c4<4;c4++)
        mma_chunk(As + c4*ACH, Ws + c4*32*132, n0w, g, tig, acc);

    #pragma unroll
    for (int ni=0;ni<2;ni++) {
        int col = n0w + ni*8 + tig*2;
        float b0 = bias[col], b1v = bias[col+1];
        #pragma unroll
        for (int mi=0;mi<2;mi++) {
            int row = m0 + mi*16 + g;
            if (row < M)
                *(float2*)(C + (size_t)row*128 + col) =
                    make_float2(acc[mi][ni][0]+b0, acc[mi][ni][1]+b1v);
            if (row + 8 < M)
                *(float2*)(C + (size_t)(row+8)*128 + col) =
                    make_float2(acc[mi][ni][2]+b0, acc[mi][ni][3]+b1v);
        }
    }
}

// ---------------- QKV (tf32 mma, full staging) ----------------
__global__ void __launch_bounds__(256) qkv_gemm_kernel(
    const float* __restrict__ Wq, const float* __restrict__ bq,
    const float* __restrict__ Wk, const float* __restrict__ bk,
    const float* __restrict__ Wv, const float* __restrict__ bv)
{
    const float *W, *bias; float* C;
    if (blockIdx.z == 0)      { W=Wq; bias=bq; C=g_Q; }
    else if (blockIdx.z == 1) { W=Wk; bias=bk; C=g_K; }
    else                      { W=Wv; bias=bv; C=g_V; }
    const int m0 = blockIdx.x * 32;

    extern __shared__ float sm[];
    float* Ws = sm;
    float* As = sm + 128*132;

    const int tid = threadIdx.x;
    const int lane = tid & 31, warp = tid >> 5;
    const int g = lane >> 2, tig = lane & 3;
    const int n0w = warp * 16;

    #pragma unroll
    for (int u=0;u<4;u++) {
        int e = u*1024 + tid*4;
        int row = e >> 7, col = e & 127;
        int grow = m0 + row;
        float4 a4 = make_float4(0.f,0.f,0.f,0.f);
        if (grow < MTR) a4 = *(const float4*)(g_X + (size_t)grow*128 + col);
        int chunk = col >> 5;
        *(float4*)&As[chunk*ACH + row*36 + (col & 31)] =
            make_float4(f2tf(a4.x), f2tf(a4.y), f2tf(a4.z), f2tf(a4.w));
    }
    stage_Wfull(Ws, W, tid);
    __syncthreads();

    float acc[2][2][4];
    #pragma unroll
    for (int a=0;a<2;a++)
        #pragma unroll
        for (int b=0;b<2;b++)
            #pragma unroll
            for (int c=0;c<4;c++) acc[a][b][c] = 0.f;

    #pragma unroll
    for (int c4=0;c4<4;c4++)
        mma_chunk(As + c4*ACH, Ws + c4*32*132, n0w, g, tig, acc);

    #pragma unroll
    for (int ni=0;ni<2;ni++) {
        int col = n0w + ni*8 + tig*2;
        float b0 = bias[col], b1v = bias[col+1];
        #pragma unroll
        for (int mi=0;mi<2;mi++) {
            int row = m0 + mi*16 + g;
            if (row < MTR)
                *(float2*)(C + (size_t)row*128 + col) =
                    make_float2(acc[mi][ni][0]+b0, acc[mi][ni][1]+b1v);
            if (row + 8 < MTR)
                *(float2*)(C + (size_t)(row+8)*128 + col) =
                    make_float2(acc[mi][ni][2]+b0, acc[mi][ni][3]+b1v);
        }
    }
}

// ---------------- masked per-channel attention (mTA), both heads per block ----------------
__global__ void __launch_bounds__(256, 1)
mta_kernel(const float* __restrict__ Qmain, const float* __restrict__ Qcls,
           const float* __restrict__ K, const float* __restrict__ X,
           float* __restrict__ o32main, float* __restrict__ o32cls)
{
    const int b = blockIdx.y;
    const bool cls = blockIdx.x >= 8;
    const int tile = cls ? (blockIdx.x - 8) : blockIdx.x;
    const float* Q = cls ? Qcls : Qmain;
    const int qStride = cls ? 0 : NL*128;
    const int Lq = cls ? 128 : NL;
    float* o32 = cls ? o32cls : o32main;

    const int tid = threadIdx.x;
    const int head = tid >> 7;
    const int wt = tid & 127;
    const int lane = wt & 31, warp = wt >> 5;
    const int qi = tile*64 + warp*16 + (lane & 15);
    const int half = lane >> 4;

    __shared__ float sK[2][2][2][16][64];
    __shared__ float sX[2][2][16][16];

    float4 qreg[16];
    const float* qp = Q + (size_t)b*qStride + (size_t)qi*128 + head*64;
    #pragma unroll
    for (int i=0;i<16;i++) qreg[i] = *(const float4*)(qp + i*4);

    float m = -1e30f;
    float den[8], num[8];
    #pragma unroll
    for (int c=0;c<8;c++){ den[c]=0.f; num[c]=0.f; }

    auto loadChunk = [&](int c, int bf) {
        #pragma unroll
        for (int u=0;u<4;u++) {
            int e = u*1024 + tid*4;
            int hd = e>>11, hh = (e>>10)&1, kk = (e>>6)&15, d = e&63;
            int kglob = hh*256 + c*16 + kk;
            *(float4*)&sK[bf][hd][hh][kk][d] =
                *(const float4*)(K + ((size_t)b*NL + kglob)*128 + hd*64 + d);
        }
        if (tid < 128) {
            int e = tid*4;
            int hh = e>>8, kk = (e>>4)&15, d = e&15;
            int kglob = hh*256 + c*16 + kk;
            *(float4*)&sX[bf][hh][kk][d] =
                *(const float4*)(X + ((size_t)b*NL + kglob)*16 + d);
        }
    };

    loadChunk(0, 0);
    __syncthreads();
    for (int c=0;c<16;c++) {
        const int cur = c & 1;
        if (c < 15) loadChunk(c+1, cur^1);
        #pragma unroll 2
        for (int kk=0;kk<16;kk+=2) {
            const float4* kr0 = (const float4*)sK[cur][head][half][kk];
            const float4* kr1 = (const float4*)sK[cur][head][half][kk+1];
            float4 A0 = make_float4(0.f,0.f,0.f,0.f);
            float4 A1 = make_float4(0.f,0.f,0.f,0.f);
            #pragma unroll
            for (int i=0;i<16;i++) {
                float4 k0 = kr0[i], k1 = kr1[i];
                float4 q = qreg[i];
                A0.x = fmaf(k0.x, q.x, A0.x); A1.x = fmaf(k1.x, q.x, A1.x);
                A0.y = fmaf(k0.y, q.y, A0.y); A1.y = fmaf(k1.y, q.y, A1.y);
                A0.z = fmaf(k0.z, q.z, A0.z); A1.z = fmaf(k1.z, q.z, A1.z);
                A0.w = fmaf(k0.w, q.w, A0.w); A1.w = fmaf(k1.w, q.w, A1.w);
            }
            float s0 = ((A0.x+A0.y)+(A0.z+A0.w))*0.125f;
            float s1 = ((A1.x+A1.y)+(A1.z+A1.w))*0.125f;
            float mx = fmaxf(m, fmaxf(s0, s1));
            if (mx > m) {
                float f = fexp(m - mx);
                #pragma unroll
                for (int cc=0;cc<8;cc++){ den[cc]*=f; num[cc]*=f; }
                m = mx;
            }
            float e0 = fexp(s0 - m), e1 = fexp(s1 - m);
            const float* x0 = sX[cur][half][kk];
            const float* x1 = sX[cur][half][kk+1];
            #pragma unroll
            for (int cc=0;cc<8;cc++) {
                float t0 = e0 * x0[8+cc];
                float t1 = e1 * x1[8+cc];
                den[cc] += t0 + t1;
                num[cc] = fmaf(t0, x0[cc], fmaf(t1, x1[cc], num[cc]));
            }
        }
        __syncthreads();
    }
    float m2 = __shfl_xor_sync(0xffffffffu, m, 16);
    float Mx = fmaxf(m, m2);
    float f1 = fexp(m - Mx), f2 = fexp(m2 - Mx);
    #pragma unroll
    for (int cc=0;cc<8;cc++) {
        float d2 = __shfl_xor_sync(0xffffffffu, den[cc], 16);
        float n2 = __shfl_xor_sync(0xffffffffu, num[cc], 16);
        den[cc] = den[cc]*f1 + d2*f2;
        num[cc] = num[cc]*f1 + n2*f2;
    }
    if (half == 0) {
        float res[16];
        #pragma unroll
        for (int cc=0;cc<8;cc++) {
            bool ok = den[cc] > 0.f;
            res[cc]   = ok ? num[cc]/den[cc] : 0.f;
            res[8+cc] = ok ? 1.f : 0.f;
        }
        float* dst = o32 + ((size_t)b*Lq + qi)*32 + head*16;
        #pragma unroll
        for (int i=0;i<4;i++)
            *(float4*)(dst + i*4) = make_float4(res[i*4],res[i*4+1],res[i*4+2],res[i*4+3]);
    }
}

// ---------------- 32->128 projection into merged X + cls-row fill ----------------
__global__ void proj32_kernel(const float* __restrict__ Am, const float* __restrict__ Ac,
                              const float* __restrict__ W, const float* __restrict__ bias,
                              const float* __restrict__ pos, const float* __restrict__ cls_emb)
{
    if (blockIdx.x == 320) {
        for (int i = threadIdx.x; i < 1024; i += 256) {
            int b = i >> 7, j = i & 127;
            float cv = cls_emb[j];
            g_X[((size_t)b*NT1)*128 + j] = cv;
            g_X[((size_t)M1R + (size_t)b*NT2)*128 + j] = cv + pos[j];
        }
        return;
    }
    __shared__ float sWT[128*36];
    __shared__ float sA[16*32];
    const bool cls = blockIdx.x >= 256;
    const float* A = cls ? Ac : Am;
    const int Lq = cls ? 128 : NL;
    const int r0 = (cls ? (blockIdx.x - 256) : blockIdx.x) * 16;
    for (int i = threadIdx.x; i < 4096; i += 256) {
        int r = i >> 7, c = i & 127;
        sWT[c*36 + r] = W[i];
    }
    for (int i = threadIdx.x; i < 512; i += 256)
        sA[i] = A[(size_t)(r0 + (i >> 5))*32 + (i & 31)];
    __syncthreads();
    #pragma unroll
    for (int u=0;u<8;u++) {
        int oi = threadIdx.x + u*256;
        int lr = oi >> 7, col = oi & 127;
        int r = r0 + lr;
        float acc = bias[col];
        const float4* wp = (const float4*)&sWT[col*36];
        const float4* ap = (const float4*)&sA[lr*32];
        #pragma unroll
        for (int k8=0;k8<8;k8++) {
            float4 w = wp[k8];
            float4 a = ap[k8];
            acc = fmaf(a.x, w.x, acc);
            acc = fmaf(a.y, w.y, acc);
            acc = fmaf(a.z, w.z, acc);
            acc = fmaf(a.w, w.w, acc);
        }
        int bb = r / Lq, q = r % Lq;
        size_t row;
        if (cls) row = (size_t)bb*NT1 + 1 + q;
        else   { row = (size_t)M1R + (size_t)bb*NT2 + 1 + q; acc += pos[(size_t)(1+q)*128 + col]; }
        g_X[row*128 + col] = acc;
    }
}

// ---------------- tblock attention PARTIALS: key-segmented across blocks ----------------
__global__ void __launch_bounds__(128, 1) tattn_part_kernel()
{
    const int y = blockIdx.y;
    const int part = y >> 4;
    const int bh = y & 15, b = bh >> 1, head = bh & 1;
    const int T = part ? NT2 : NT1;
    const int base = part ? (M1R + b*NT2) : (b*NT1);
    if (blockIdx.x * 64 >= T) return;
    const int seg = blockIdx.z;
    const int nseg = part ? 4 : 1;
    if (seg >= nseg) return;

    const int segStart = seg * SEGL;
    const int segLen = min(SEGL, T - segStart);
    const int half0 = (segLen + 1) >> 1;

    __shared__ float sK[2][2][16][64];   // buf, half, key, dim
    __shared__ float sV[2][2][16][64];

    const int tid = threadIdx.x;
    const int lane = tid & 31, warp = tid >> 5;
    const int qi = blockIdx.x*64 + warp*16 + (lane & 15);
    const int half = lane >> 4;

    float4 qreg[16];
    if (qi < T) {
        const float* qp = g_Q + ((size_t)base + qi)*128 + head*64;
        #pragma unroll
        for (int i=0;i<16;i++) qreg[i] = *(const float4*)(qp + i*4);
    } else {
        #pragma unroll
        for (int i=0;i<16;i++) qreg[i] = make_float4(0.f,0.f,0.f,0.f);
    }
    float m = -1e30f, l = 0.f;
    float o[64];
    #pragma unroll
    for (int d=0;d<64;d++) o[d]=0.f;

    const int myStart = half ? half0 : 0;
    const int myEnd   = half ? segLen : half0;
    const int nch = (half0 + 15) >> 4;

    auto loadChunk = [&](int c, int bf) {
        #pragma unroll
        for (int u=0;u<8;u++) {
            int idx4 = tid*8 + u;           // 0..1023 float4s (K then V)
            int isV = idx4 >> 9;
            int r = idx4 & 511;
            int hh = r >> 8, kk = (r >> 4) & 15, d = (r & 15) * 4;
            int klocal = (hh ? half0 : 0) + c*16 + kk;
            int lim = hh ? segLen : half0;
            float4 v = make_float4(0.f,0.f,0.f,0.f);
            if (klocal < lim) {
                const float* src = (isV ? g_V : g_K) +
                    ((size_t)base + segStart + klocal)*128 + head*64 + d;
                v = *(const float4*)src;
            }
            float* dst = (isV ? &sV[bf][hh][kk][d] : &sK[bf][hh][kk][d]);
            *(float4*)dst = v;
        }
    };

    loadChunk(0, 0);
    __syncthreads();
    for (int c=0;c<nch;c++) {
        const int cur = c & 1;
        if (c+1 < nch) loadChunk(c+1, cur^1);
        const int k0 = myStart + c*16;
        const float* sKh = &sK[cur][half][0][0];
        const float* sVh = &sV[cur][half][0][0];
        #pragma unroll 2
        for (int kk=0;kk<16;kk+=2) {
            const float4* kr0 = (const float4*)(sKh + kk*64);
            const float4* kr1 = (const float4*)(sKh + (kk+1)*64);
            float4 A0 = make_float4(0.f,0.f,0.f,0.f);
            float4 A1 = make_float4(0.f,0.f,0.f,0.f);
            #pragma unroll
            for (int i=0;i<16;i++) {
                float4 k0v = kr0[i], k1v = kr1[i];
                float4 q = qreg[i];
                A0.x = fmaf(k0v.x, q.x, A0.x); A1.x = fmaf(k1v.x, q.x, A1.x);
                A0.y = fmaf(k0v.y, q.y, A0.y); A1.y = fmaf(k1v.y, q.y, A1.y);
                A0.z = fmaf(k0v.z, q.z, A0.z); A1.z = fmaf(k1v.z, q.z, A1.z);
                A0.w = fmaf(k0v.w, q.w, A0.w); A1.w = fmaf(k1v.w, q.w, A1.w);
            }
            float s0 = ((A0.x+A0.y)+(A0.z+A0.w))*0.125f;
            float s1 = ((A1.x+A1.y)+(A1.z+A1.w))*0.125f;
            bool v0 = (k0 + kk < myEnd), v1 = (k0 + kk + 1 < myEnd);
            float mx = m;
            if (v0) mx = fmaxf(mx, s0);
            if (v1) mx = fmaxf(mx, s1);
            if (mx > m) {
                float f = fexp(m - mx);
                l *= f;
                #pragma unroll
                for (int d=0;d<64;d++) o[d]*=f;
                m = mx;
            }
            float e0 = v0 ? fexp(s0 - m) : 0.f;
            float e1 = v1 ? fexp(s1 - m) : 0.f;
            l += e0 + e1;
            const float4* vr0 = (const float4*)(sVh + kk*64);
            const float4* vr1 = (const float4*)(sVh + (kk+1)*64);
            #pragma unroll
            for (int i=0;i<16;i++) {
                float4 w0 = vr0[i], w1 = vr1[i];
                o[i*4+0] = fmaf(e0, w0.x, fmaf(e1, w1.x, o[i*4+0]));
                o[i*4+1] = fmaf(e0, w0.y, fmaf(e1, w1.y, o[i*4+1]));
                o[i*4+2] = fmaf(e0, w0.z, fmaf(e1, w1.z, o[i*4+2]));
                o[i*4+3] = fmaf(e0, w0.w, fmaf(e1, w1.w, o[i*4+3]));
            }
        }
        __syncthreads();
    }
    // merge the two halves (partner = lane ^ 16)
    float m2 = __shfl_xor_sync(0xffffffffu, m, 16);
    float Mx = fmaxf(m, m2);
    float f1 = fexp(m - Mx), f2 = fexp(m2 - Mx);
    float l2 = __shfl_xor_sync(0xffffffffu, l, 16);
    l = l*f1 + l2*f2;
    #pragma unroll
    for (int d=0;d<64;d++) {
        float o2 = __shfl_xor_sync(0xffffffffu, o[d], 16);
        o[d] = o[d]*f1 + o2*f2;
    }
    if (half == 0 && qi < T) {
        float* pp = g_part + (((size_t)(base + qi)*2 + head)*4 + seg)*PREC;
        pp[0] = Mx;
        pp[1] = l;
        #pragma unroll
        for (int i=0;i<16;i++)
            *(float4*)(pp + 4 + i*4) = make_float4(o[i*4],o[i*4+1],o[i*4+2],o[i*4+3]);
    }
}

// ---------------- MERGE partials + Wo GEMM + residual + LN1 → X2 ----------------
__global__ void __launch_bounds__(256, 1) merge_ln_kernel(
    const float* __restrict__ tWo, const float* __restrict__ tbo,
    const float* __restrict__ lng, const float* __restrict__ lnb)
{
    extern __shared__ float sm[];
    float* Ws = sm;
    float* As = sm + 128*132;
    float* F  = sm + 128*132 + 4*ACH;

    const int m0 = blockIdx.x * 32;
    const int tid = threadIdx.x;
    const int lane = tid & 31, warp = tid >> 5;
    const int g = lane >> 2, tig = lane & 3;
    const int n0w = warp * 16;

    // ---- merge preamble: quad per (row, head); each of 4 threads does 16 dims ----
    {
        const int pair = tid >> 2;          // 0..63
        const int lr = pair >> 1;           // 0..31
        const int head = pair & 1;
        const int d0 = (tid & 3) * 16;
        const int r = m0 + lr;
        if (r < MTR) {
            const int nseg = (r < M1R) ? 1 : 4;
            const float* pp = g_part + ((size_t)r*2 + head)*4*PREC;
            float ms = pp[0];
            for (int s=1; s<nseg; s++) ms = fmaxf(ms, pp[s*PREC]);
            float f[4]; float L = 0.f;
            for (int s=0; s<nseg; s++) { f[s] = fexp(pp[s*PREC] - ms); L = fmaf(pp[s*PREC+1], f[s], L); }
            float invL = 1.0f / L;
            for (int dd=0; dd<16; dd++) {
                int d = d0 + dd;
                float acc = 0.f;
                for (int s=0; s<nseg; s++) acc = fmaf(pp[s*PREC + 4 + d], f[s], acc);
                int col = head*64 + d;
                As[(col >> 5)*ACH + lr*36 + (col & 31)] = f2tf(acc * invL);
            }
        } else {
            for (int dd=0; dd<16; dd++) {
                int col = head*64 + d0 + dd;
                As[(col >> 5)*ACH + lr*36 + (col & 31)] = 0.f;
            }
        }
    }
    stage_Wfull(Ws, tWo, tid);
    __syncthreads();

    float acc[2][2][4];
    #pragma unroll
    for (int a=0;a<2;a++)
        #pragma unroll
        for (int b=0;b<2;b++)
            #pragma unroll
            for (int c=0;c<4;c++) acc[a][b][c] = 0.f;

    #pragma unroll
    for (int c4=0;c4<4;c4++)
        mma_chunk(As + c4*ACH, Ws + c4*32*132, n0w, g, tig, acc);
    __syncthreads();

    #pragma unroll
    for (int ni=0;ni<2;ni++) {
        int col = n0w + ni*8 + tig*2;
        float b0 = tbo[col], b1v = tbo[col+1];
        #pragma unroll
        for (int mi=0;mi<2;mi++) {
            int row = mi*16 + g;
            F[row*132 + col]       = acc[mi][ni][0]+b0;
            F[row*132 + col+1]     = acc[mi][ni][1]+b1v;
            F[(row+8)*132 + col]   = acc[mi][ni][2]+b0;
            F[(row+8)*132 + col+1] = acc[mi][ni][3]+b1v;
        }
    }
    __syncthreads();

    float4 g4 = *(const float4*)(lng + lane*4);
    float4 be4 = *(const float4*)(lnb + lane*4);
    #pragma unroll
    for (int i=0;i<4;i++) {
        int row = warp*4 + i;
        int r = m0 + row;
        if (r >= MTR) continue;
        float4 fv = *(const float4*)&F[row*132 + lane*4];
        float4 rv = *(const float4*)(g_X + (size_t)r*128 + lane*4);
        float v[4] = {fv.x+rv.x, fv.y+rv.y, fv.z+rv.z, fv.w+rv.w};
        float s = v[0]+v[1]+v[2]+v[3];
        float s2 = v[0]*v[0]+v[1]*v[1]+v[2]*v[2]+v[3]*v[3];
        #pragma unroll
        for (int off=16; off>0; off>>=1) {
            s  += __shfl_xor_sync(0xffffffffu, s,  off);
            s2 += __shfl_xor_sync(0xffffffffu, s2, off);
        }
        float mean = s * (1.f/128.f);
        float var  = s2 * (1.f/128.f) - mean*mean;
        float rs   = rsqrtf(var + 1e-5f);
        float4 ov;
        ov.x = (v[0]-mean)*rs*g4.x + be4.x;
        ov.y = (v[1]-mean)*rs*g4.y + be4.y;
        ov.z = (v[2]-mean)*rs*g4.z + be4.z;
        ov.w = (v[3]-mean)*rs*g4.w + be4.w;
        *(float4*)(g_X2 + (size_t)r*128 + lane*4) = ov;
    }
}

// ---------------- FUSED FFN (tf32 mma, full staging) + LN2 + inline pooling ----------
__global__ void __launch_bounds__(256, 1) ffn_kernel(
    const float* __restrict__ fW1, const float* __restrict__ fb1,
    const float* __restrict__ fW2, const float* __restrict__ fb2,
    const float* __restrict__ lng, const float* __restrict__ lnb,
    const float* __restrict__ pW, const float* __restrict__ pb,
    float* __restrict__ dpool, float* __restrict__ dlast)
{
    extern __shared__ float sm[];
    float* Ws = sm;
    float* As = sm + 128*132;
    float* F  = sm + 128*132 + 4*ACH;

    const int m0 = blockIdx.x * 32;
    const int tid = threadIdx.x;
    const int lane = tid & 31, warp = tid >> 5;
    const int g = lane >> 2, tig = lane & 3;
    const int n0w = warp * 16;

    float acc[2][2][4];
    #pragma unroll
    for (int a=0;a<2;a++)
        #pragma unroll
        for (int b=0;b<2;b++)
            #pragma unroll
            for (int c=0;c<4;c++) acc[a][b][c] = 0.f;

    #pragma unroll
    for (int u=0;u<4;u++) {
        int e = u*1024 + tid*4;
        int row = e >> 7, col = e & 127;
        int grow = m0 + row;
        float4 a4 = make_float4(0.f,0.f,0.f,0.f);
        if (grow < MTR) a4 = *(const float4*)(g_X2 + (size_t)grow*128 + col);
        int chunk = col >> 5;
        *(float4*)&As[chunk*ACH + row*36 + (col & 31)] =
            make_float4(f2tf(a4.x), f2tf(a4.y), f2tf(a4.z), f2tf(a4.w));
    }
    stage_Wfull(Ws, fW1, tid);
    __syncthreads();

    #pragma unroll
    for (int c4=0;c4<4;c4++)
        mma_chunk(As + c4*ACH, Ws + c4*32*132, n0w, g, tig, acc);
    __syncthreads();

    #pragma unroll
    for (int ni=0;ni<2;ni++) {
        int col = n0w + ni*8 + tig*2;
        float b0 = fb1[col], b1v = fb1[col+1];
        #pragma unroll
        for (int mi=0;mi<2;mi++) {
            int row = mi*16 + g;
            F[row*132 + col]       = f2tf(fmaxf(acc[mi][ni][0]+b0,  0.f));
            F[row*132 + col+1]     = f2tf(fmaxf(acc[mi][ni][1]+b1v, 0.f));
            F[(row+8)*132 + col]   = f2tf(fmaxf(acc[mi][ni][2]+b0,  0.f));
            F[(row+8)*132 + col+1] = f2tf(fmaxf(acc[mi][ni][3]+b1v, 0.f));
        }
    }
    stage_Wfull(Ws, fW2, tid);
    __syncthreads();

    #pragma unroll
    for (int a=0;a<2;a++)
        #pragma unroll
        for (int b=0;b<2;b++)
            #pragma unroll
            for (int c=0;c<4;c++) acc[a][b][c] = 0.f;

    #pragma unroll
    for (int c4=0;c4<4;c4++)
        mma_chunk_F(F, c4*32, Ws + c4*32*132, n0w, g, tig, acc);
    __syncthreads();

    #pragma unroll
    for (int ni=0;ni<2;ni++) {
        int col = n0w + ni*8 + tig*2;
        float b0 = fb2[col], b1v = fb2[col+1];
        #pragma unroll
        for (int mi=0;mi<2;mi++) {
            int row = mi*16 + g;
            F[row*132 + col]       = acc[mi][ni][0]+b0;
            F[row*132 + col+1]     = acc[mi][ni][1]+b1v;
            F[(row+8)*132 + col]   = acc[mi][ni][2]+b0;
            F[(row+8)*132 + col+1] = acc[mi][ni][3]+b1v;
        }
    }
    __syncthreads();

    float4 g4 = *(const float4*)(lng + lane*4);
    float4 be4 = *(const float4*)(lnb + lane*4);
    #pragma unroll
    for (int i=0;i<4;i++) {
        int row = warp*4 + i;
        int r = m0 + row;
        if (r >= MTR) continue;
        float4 fv = *(const float4*)&F[row*132 + lane*4];
        float4 rv = *(const float4*)(g_X2 + (size_t)r*128 + lane*4);
        float v[4] = {fv.x+rv.x, fv.y+rv.y, fv.z+rv.z, fv.w+rv.w};
        float s = v[0]+v[1]+v[2]+v[3];
        float s2 = v[0]*v[0]+v[1]*v[1]+v[2]*v[2]+v[3]*v[3];
        #pragma unroll
        for (int off=16; off>0; off>>=1) {
            s  += __shfl_xor_sync(0xffffffffu, s,  off);
            s2 += __shfl_xor_sync(0xffffffffu, s2, off);
        }
        float mean = s * (1.f/128.f);
        float var  = s2 * (1.f/128.f) - mean*mean;
        float rs   = rsqrtf(var + 1e-5f);
        float4 ov;
        ov.x = (v[0]-mean)*rs*g4.x + be4.x;
        ov.y = (v[1]-mean)*rs*g4.y + be4.y;
        ov.z = (v[2]-mean)*rs*g4.z + be4.z;
        ov.w = (v[3]-mean)*rs*g4.w + be4.w;
        if (r < M1R) {
            if (r % NT1 == 0) {
                int bidx = r / NT1;
                *(float4*)&As[lane*4] = ov;
                __syncwarp();
                float4 accp = *(const float4*)(pb + lane*4);
                for (int k=0;k<128;k++) {
                    float sv = As[k];
                    float4 w = *(const float4*)(pW + (size_t)k*128 + lane*4);
                    accp.x = fmaf(sv, w.x, accp.x);
                    accp.y = fmaf(sv, w.y, accp.y);
                    accp.z = fmaf(sv, w.z, accp.z);
                    accp.w = fmaf(sv, w.w, accp.w);
                }
                float4 outv;
                outv.x = tanhf(accp.x); outv.y = tanhf(accp.y);
                outv.z = tanhf(accp.z); outv.w = tanhf(accp.w);
                *(float4*)(dpool + (size_t)bidx*128 + lane*4) = outv;
            }
        } else {
            int rr = r - M1R;
            int t  = rr % NT2;
            if (t == 0) continue;
            int b  = rr / NT2;
            *(float4*)(dlast + ((size_t)b*NL + t - 1)*128 + lane*4) = ov;
        }
    }
}

// ---------------- launch ----------------
extern "C" void kernel_launch(void* const* d_in, const int* in_sizes, int n_in,
                              void* d_out, int out_size)
{
    (void)in_sizes; (void)n_in; (void)out_size;
    const float* x       = (const float*)d_in[0];
    const float* ts      = (const float*)d_in[1];
    const float* w_per   = (const float*)d_in[2];
    const float* b_per   = (const float*)d_in[3];
    const float* w_lin   = (const float*)d_in[4];
    const float* b_lin   = (const float*)d_in[5];
    const float* Wq_t    = (const float*)d_in[6];
    const float* bq_t    = (const float*)d_in[7];
    const float* Wk_t    = (const float*)d_in[8];
    const float* bk_t    = (const float*)d_in[9];
    const float* Wo_t    = (const float*)d_in[10];
    const float* bo_t    = (const float*)d_in[11];
    const float* pos_emb = (const float*)d_in[12];
    const float* cls_emb = (const float*)d_in[13];
    const float* tWq = (const float*)d_in[14];
    const float* tbq = (const float*)d_in[15];
    const float* tWk = (const float*)d_in[16];
    const float* tbk = (const float*)d_in[17];
    const float* tWv = (const float*)d_in[18];
    const float* tbv = (const float*)d_in[19];
    const float* tWo = (const float*)d_in[20];
    const float* tbo = (const float*)d_in[21];
    const float* ln1_g = (const float*)d_in[22];
    const float* ln1_b = (const float*)d_in[23];
    const float* fW1 = (const float*)d_in[24];
    const float* fb1 = (const float*)d_in[25];
    const float* fW2 = (const float*)d_in[26];
    const float* fb2 = (const float*)d_in[27];
    const float* ln2_g = (const float*)d_in[28];
    const float* ln2_b = (const float*)d_in[29];
    const float* pW  = (const float*)d_in[30];
    const float* pb  = (const float*)d_in[31];
    float* dout = (float*)d_out;

    float *Qb, *Kb, *Qc, *o32a, *o32c;
    cudaGetSymbolAddress((void**)&Qb,   g_Qb);
    cudaGetSymbolAddress((void**)&Kb,   g_Kb);
    cudaGetSymbolAddress((void**)&Qc,   g_Qc);
    cudaGetSymbolAddress((void**)&o32a, g_o32a);
    cudaGetSymbolAddress((void**)&o32c, g_o32c);

    const int GEMM_SMEM = (128*132 + 4*ACH) * 4;                 // 86016 B
    cudaFuncSetAttribute(kq_gemm_kernel,  cudaFuncAttributeMaxDynamicSharedMemorySize, GEMM_SMEM);
    cudaFuncSetAttribute(qkv_gemm_kernel, cudaFuncAttributeMaxDynamicSharedMemorySize, GEMM_SMEM);
    const int BIG_SMEM = (128*132 + 4*ACH + 32*132) * 4;         // 102912 B
    cudaFuncSetAttribute(merge_ln_kernel, cudaFuncAttributeMaxDynamicSharedMemorySize, BIG_SMEM);
    cudaFuncSetAttribute(ffn_kernel,      cudaFuncAttributeMaxDynamicSharedMemorySize, BIG_SMEM);

    // 1. K/Q projections with inline time-embedding
    kq_gemm_kernel<<<dim3(128, 1, 3), 256, GEMM_SMEM>>>(ts, w_per, b_per, w_lin, b_lin,
                                                        Wq_t, bq_t, Wk_t, bk_t);

    // 2. masked channel attention (both heads per block)
    mta_kernel<<<dim3(10, NB), 256>>>(Qb, Qc, Kb, x, o32a, o32c);

    // 3. build merged tblock input (incl. cls rows)
    proj32_kernel<<<321, 256>>>(o32a, o32c, Wo_t, bo_t, pos_emb, cls_emb);

    // 4. QKV
    qkv_gemm_kernel<<<dim3((MTR+31)/32, 1, 3), 256, GEMM_SMEM>>>(tWq, tbq, tWk, tbk, tWv, tbv);

    // 5a. attention partials, key-segmented across blocks (4x parallelism)
    tattn_part_kernel<<<dim3((NT2+63)/64, 32, 4), 128>>>();

    // 5b. merge partials + Wo + residual + LN1 → X2
    merge_ln_kernel<<<(MTR+31)/32, 256, BIG_SMEM>>>(tWo, tbo, ln1_g, ln1_b);

    // 6. fused FFN + residual + LN2 + inline cls pooling
    ffn_kernel<<<(MTR+31)/32, 256, BIG_SMEM>>>(fW1, fb1, fW2, fb2, ln2_g, ln2_b,
                                               pW, pb, dout, dout + 1024);
}

// round 17
// speedup vs baseline: 1.2565x; 1.0471x over previous
#include <cuda_runtime.h>
#include <math.h>
#include <stdint.h>

#define NB 8
#define NL 512
#define NE 128
#define NT1 129
#define NT2 513
#define M1R (NB*NT1)        // 1032
#define M2R (NB*NT2)        // 4104
#define MTR (M1R+M2R)       // 5136
#define ACH (32*36)         // one A chunk (32 rows x 32 cols, pitch 36)
#define SEGL 129            // tattn key segment length
#define PREC 68             // g_part record: [m, l, pad, pad, o[64]]
#define MQT 640             // mta q rows per batch (512 main + 128 cls)
#define MREC 20             // mta partial record: [m, pad x3, den[8], num[8]]

// ---------------- device scratch ----------------
__device__ float g_Qb   [NB*NL*NE];
__device__ float g_Kb   [NB*NL*NE];
__device__ float g_Qc   [128*NE];
__device__ float g_X    [MTR*128];
__device__ float g_Q    [MTR*128];
__device__ float g_K    [MTR*128];
__device__ float g_V    [MTR*128];
__device__ float g_X2   [MTR*128];
__device__ __align__(16) float g_part [MTR*2*4*PREC];     // tattn partials
__device__ __align__(16) float g_mpart[NB*MQT*2*4*MREC];  // mta partials

// ---------------- fast exp on FMA/ALU pipes (args <= 0) ----------------
__device__ __forceinline__ float fexp(float x)
{
    x = fmaxf(x, -80.0f);
    float t  = x * 1.4426950408889634f;
    float kf = t + 12582912.0f;
    int   k  = __float_as_int(kf) - 0x4B400000;
    float f  = t - (kf - 12582912.0f);
    float p  = 1.3333558e-3f;
    p = fmaf(p, f, 9.6181291e-3f);
    p = fmaf(p, f, 5.5504109e-2f);
    p = fmaf(p, f, 2.4022651e-1f);
    p = fmaf(p, f, 6.9314718e-1f);
    p = fmaf(p, f, 1.0f);
    return __int_as_float(__float_as_int(p) + (k << 23));
}

// ---------------- tf32 helpers ----------------
__device__ __forceinline__ float f2tf(float f)
{
    uint32_t r;
    asm("cvt.rna.tf32.f32 %0, %1;" : "=r"(r) : "f"(f));
    return __uint_as_float(r);
}

__device__ __forceinline__ void mma8(float* c, uint32_t a0, uint32_t a1, uint32_t a2, uint32_t a3,
                                     uint32_t b0, uint32_t b1)
{
    asm volatile("mma.sync.aligned.m16n8k8.row.col.f32.tf32.tf32.f32 "
                 "{%0,%1,%2,%3}, {%4,%5,%6,%7}, {%8,%9}, {%0,%1,%2,%3};"
                 : "+f"(c[0]), "+f"(c[1]), "+f"(c[2]), "+f"(c[3])
                 : "r"(a0), "r"(a1), "r"(a2), "r"(a3), "r"(b0), "r"(b1));
}

__device__ __forceinline__ void mma_chunk(const float* As, const float* Ws,
                                          int n0w, int g, int tig, float acc[2][2][4])
{
    #pragma unroll
    for (int j=0;j<4;j++) {
        uint32_t a[2][4];
        #pragma unroll
        for (int mi=0;mi<2;mi++) {
            int rb = mi*16;
            a[mi][0] = __float_as_uint(As[(rb+g)*36   + j*8+tig]);
            a[mi][1] = __float_as_uint(As[(rb+g+8)*36 + j*8+tig]);
            a[mi][2] = __float_as_uint(As[(rb+g)*36   + j*8+tig+4]);
            a[mi][3] = __float_as_uint(As[(rb+g+8)*36 + j*8+tig+4]);
        }
        #pragma unroll
        for (int ni=0;ni<2;ni++) {
            int cb = n0w + ni*8 + g;
            uint32_t b0 = __float_as_uint(Ws[(j*8+tig)*132   + cb]);
            uint32_t b1 = __float_as_uint(Ws[(j*8+tig+4)*132 + cb]);
            mma8(acc[0][ni], a[0][0],a[0][1],a[0][2],a[0][3], b0,b1);
            mma8(acc[1][ni], a[1][0],a[1][1],a[1][2],a[1][3], b0,b1);
        }
    }
}

__device__ __forceinline__ void mma_chunk_F(const float* F, int kc, const float* Ws,
                                            int n0w, int g, int tig, float acc[2][2][4])
{
    #pragma unroll
    for (int j=0;j<4;j++) {
        uint32_t a[2][4];
        #pragma unroll
        for (int mi=0;mi<2;mi++) {
            int rb = mi*16;
            a[mi][0] = __float_as_uint(F[(rb+g)*132   + kc + j*8+tig]);
            a[mi][1] = __float_as_uint(F[(rb+g+8)*132 + kc + j*8+tig]);
            a[mi][2] = __float_as_uint(F[(rb+g)*132   + kc + j*8+tig+4]);
            a[mi][3] = __float_as_uint(F[(rb+g+8)*132 + kc + j*8+tig+4]);
        }
        #pragma unroll
        for (int ni=0;ni<2;ni++) {
            int cb = n0w + ni*8 + g;
            uint32_t b0 = __float_as_uint(Ws[(j*8+tig)*132   + cb]);
            uint32_t b1 = __float_as_uint(Ws[(j*8+tig+4)*132 + cb]);
            mma8(acc[0][ni], a[0][0],a[0][1],a[0][2],a[0][3], b0,b1);
            mma8(acc[1][ni], a[1][0],a[1][1],a[1][2],a[1][3], b0,b1);
        }
    }
}

__device__ __forceinline__ void stage_Wfull(float* Ws, const float* W, int tid)
{
    #pragma unroll
    for (int u=0;u<16;u++) {
        int e = u*1024 + tid*4;
        int r = e >> 7, c = e & 127;
        float4 w4 = *(const float4*)(W + (size_t)r*128 + c);
        *(float4*)&Ws[r*132 + c] =
            make_float4(f2tf(w4.x), f2tf(w4.y), f2tf(w4.z), f2tf(w4.w));
    }
}

// ---------------- K/Q projections with inline time-embedding ----------
__global__ void __launch_bounds__(256) kq_gemm_kernel(
    const float* __restrict__ ts,
    const float* __restrict__ w_per, const float* __restrict__ b_per,
    const float* __restrict__ w_lin, const float* __restrict__ b_lin,
    const float* __restrict__ Wq, const float* __restrict__ bq,
    const float* __restrict__ Wk, const float* __restrict__ bk)
{
    const int z = blockIdx.z;
    const float *W, *bias; float* C; int M;
    if (z == 0)      { W=Wk; bias=bk; C=g_Kb; M=NB*NL; }
    else if (z == 1) { W=Wq; bias=bq; C=g_Qb; M=NB*NL; }
    else             { W=Wq; bias=bq; C=g_Qc; M=128;  }
    const int m0 = blockIdx.x * 32;
    if (m0 >= M) return;

    extern __shared__ float sm[];
    float* Ws = sm;
    float* As = sm + 128*132;

    const int tid = threadIdx.x;
    const int lane = tid & 31, warp = tid >> 5;
    const int g = lane >> 2, tig = lane & 3;
    const int n0w = warp * 16;

    {
        const float wl = w_lin[0], bl = b_lin[0];
        const int row = tid >> 3;
        const int col0 = (tid & 7) * 16;
        const int grow = m0 + row;
        const float tval = (grow < M) ? ((z == 2) ? (float)grow*(1.0f/127.0f) : ts[grow]) : 0.f;
        #pragma unroll
        for (int u4=0;u4<4;u4++) {
            int cb = col0 + u4*4;
            float v[4];
            #pragma unroll
            for (int u=0;u<4;u++) {
                int j = cb + u;
                v[u] = (j == 0) ? fmaf(tval, wl, bl)
                                : __sinf(fmaf(tval, w_per[j-1], b_per[j-1]));
            }
            int chunk = cb >> 5;
            *(float4*)&As[chunk*ACH + row*36 + (cb & 31)] =
                make_float4(f2tf(v[0]), f2tf(v[1]), f2tf(v[2]), f2tf(v[3]));
        }
    }
    stage_Wfull(Ws, W, tid);
    __syncthreads();

    float acc[2][2][4];
    #pragma unroll
    for (int a=0;a<2;a++)
        #pragma unroll
        for (int b=0;b<2;b++)
            #pragma unroll
            for (int c=0;c<4;c++) acc[a][b][c] = 0.f;

    #pragma unroll
    for (int c4=0;c4<4;c4++)
        mma_chunk(As + c4*ACH, Ws + c4*32*132, n0w, g, tig, acc);

    #pragma unroll
    for (int ni=0;ni<2;ni++) {
        int col = n0w + ni*8 + tig*2;
        float b0 = bias[col], b1v = bias[col+1];
        #pragma unroll
        for (int mi=0;mi<2;mi++) {
            int row = m0 + mi*16 + g;
            if (row < M)
                *(float2*)(C + (size_t)row*128 + col) =
                    make_float2(acc[mi][ni][0]+b0, acc[mi][ni][1]+b1v);
            if (row + 8 < M)
                *(float2*)(C + (size_t)(row+8)*128 + col) =
                    make_float2(acc[mi][ni][2]+b0, acc[mi][ni][3]+b1v);
        }
    }
}

// ---------------- QKV (tf32 mma, full staging) ----------------
__global__ void __launch_bounds__(256) qkv_gemm_kernel(
    const float* __restrict__ Wq, const float* __restrict__ bq,
    const float* __restrict__ Wk, const float* __restrict__ bk,
    const float* __restrict__ Wv, const float* __restrict__ bv)
{
    const float *W, *bias; float* C;
    if (blockIdx.z == 0)      { W=Wq; bias=bq; C=g_Q; }
    else if (blockIdx.z == 1) { W=Wk; bias=bk; C=g_K; }
    else                      { W=Wv; bias=bv; C=g_V; }
    const int m0 = blockIdx.x * 32;

    extern __shared__ float sm[];
    float* Ws = sm;
    float* As = sm + 128*132;

    const int tid = threadIdx.x;
    const int lane = tid & 31, warp = tid >> 5;
    const int g = lane >> 2, tig = lane & 3;
    const int n0w = warp * 16;

    #pragma unroll
    for (int u=0;u<4;u++) {
        int e = u*1024 + tid*4;
        int row = e >> 7, col = e & 127;
        int grow = m0 + row;
        float4 a4 = make_float4(0.f,0.f,0.f,0.f);
        if (grow < MTR) a4 = *(const float4*)(g_X + (size_t)grow*128 + col);
        int chunk = col >> 5;
        *(float4*)&As[chunk*ACH + row*36 + (col & 31)] =
            make_float4(f2tf(a4.x), f2tf(a4.y), f2tf(a4.z), f2tf(a4.w));
    }
    stage_Wfull(Ws, W, tid);
    __syncthreads();

    float acc[2][2][4];
    #pragma unroll
    for (int a=0;a<2;a++)
        #pragma unroll
        for (int b=0;b<2;b++)
            #pragma unroll
            for (int c=0;c<4;c++) acc[a][b][c] = 0.f;

    #pragma unroll
    for (int c4=0;c4<4;c4++)
        mma_chunk(As + c4*ACH, Ws + c4*32*132, n0w, g, tig, acc);

    #pragma unroll
    for (int ni=0;ni<2;ni++) {
        int col = n0w + ni*8 + tig*2;
        float b0 = bias[col], b1v = bias[col+1];
        #pragma unroll
        for (int mi=0;mi<2;mi++) {
            int row = m0 + mi*16 + g;
            if (row < MTR)
                *(float2*)(C + (size_t)row*128 + col) =
                    make_float2(acc[mi][ni][0]+b0, acc[mi][ni][1]+b1v);
            if (row + 8 < MTR)
                *(float2*)(C + (size_t)(row+8)*128 + col) =
                    make_float2(acc[mi][ni][2]+b0, acc[mi][ni][3]+b1v);
        }
    }
}

// ---------------- mTA PARTIALS: key-segmented (128 keys/seg), both heads ----------------
__global__ void __launch_bounds__(256, 1)
mta_part_kernel(const float* __restrict__ Qmain, const float* __restrict__ Qcls,
                const float* __restrict__ K, const float* __restrict__ X)
{
    const int b = blockIdx.y;
    const int seg = blockIdx.z;
    const bool cls = blockIdx.x >= 8;
    const int tile = cls ? (blockIdx.x - 8) : blockIdx.x;
    const float* Q = cls ? Qcls : Qmain;
    const int qStride = cls ? 0 : NL*128;

    const int tid = threadIdx.x;
    const int head = tid >> 7;
    const int wt = tid & 127;
    const int lane = wt & 31, warp = wt >> 5;
    const int qi = tile*64 + warp*16 + (lane & 15);
    const int half = lane >> 4;

    __shared__ float sK[2][2][2][16][64];   // buf, head, half, key, dim
    __shared__ float sX[2][2][16][16];      // buf, half, key, ch

    float4 qreg[16];
    const float* qp = Q + (size_t)b*qStride + (size_t)qi*128 + head*64;
    #pragma unroll
    for (int i=0;i<16;i++) qreg[i] = *(const float4*)(qp + i*4);

    float m = -1e30f;
    float den[8], num[8];
    #pragma unroll
    for (int c=0;c<8;c++){ den[c]=0.f; num[c]=0.f; }

    const int kseg0 = seg * 128;            // segment base (all 512 keys valid; segLen=128)

    auto loadChunk = [&](int c, int bf) {
        #pragma unroll
        for (int u=0;u<4;u++) {
            int e = u*1024 + tid*4;
            int hd = e>>11, hh = (e>>10)&1, kk = (e>>6)&15, d = e&63;
            int kglob = kseg0 + hh*64 + c*16 + kk;
            *(float4*)&sK[bf][hd][hh][kk][d] =
                *(const float4*)(K + ((size_t)b*NL + kglob)*128 + hd*64 + d);
        }
        if (tid < 128) {
            int e = tid*4;
            int hh = e>>8, kk = (e>>4)&15, d = e&15;
            int kglob = kseg0 + hh*64 + c*16 + kk;
            *(float4*)&sX[bf][hh][kk][d] =
                *(const float4*)(X + ((size_t)b*NL + kglob)*16 + d);
        }
    };

    loadChunk(0, 0);
    __syncthreads();
    for (int c=0;c<4;c++) {                 // 4 chunks of 16 keys per half
        const int cur = c & 1;
        if (c < 3) loadChunk(c+1, cur^1);
        #pragma unroll 2
        for (int kk=0;kk<16;kk+=2) {
            const float4* kr0 = (const float4*)sK[cur][head][half][kk];
            const float4* kr1 = (const float4*)sK[cur][head][half][kk+1];
            float4 A0 = make_float4(0.f,0.f,0.f,0.f);
            float4 A1 = make_float4(0.f,0.f,0.f,0.f);
            #pragma unroll
            for (int i=0;i<16;i++) {
                float4 k0 = kr0[i], k1 = kr1[i];
                float4 q = qreg[i];
                A0.x = fmaf(k0.x, q.x, A0.x); A1.x = fmaf(k1.x, q.x, A1.x);
                A0.y = fmaf(k0.y, q.y, A0.y); A1.y = fmaf(k1.y, q.y, A1.y);
                A0.z = fmaf(k0.z, q.z, A0.z); A1.z = fmaf(k1.z, q.z, A1.z);
                A0.w = fmaf(k0.w, q.w, A0.w); A1.w = fmaf(k1.w, q.w, A1.w);
            }
            float s0 = ((A0.x+A0.y)+(A0.z+A0.w))*0.125f;
            float s1 = ((A1.x+A1.y)+(A1.z+A1.w))*0.125f;
            float mx = fmaxf(m, fmaxf(s0, s1));
            if (mx > m) {
                float f = fexp(m - mx);
                #pragma unroll
                for (int cc=0;cc<8;cc++){ den[cc]*=f; num[cc]*=f; }
                m = mx;
            }
            float e0 = fexp(s0 - m), e1 = fexp(s1 - m);
            const float* x0 = sX[cur][half][kk];
            const float* x1 = sX[cur][half][kk+1];
            #pragma unroll
            for (int cc=0;cc<8;cc++) {
                float t0 = e0 * x0[8+cc];
                float t1 = e1 * x1[8+cc];
                den[cc] += t0 + t1;
                num[cc] = fmaf(t0, x0[cc], fmaf(t1, x1[cc], num[cc]));
            }
        }
        __syncthreads();
    }
    // merge the two key-halves (partner = lane ^ 16)
    float m2 = __shfl_xor_sync(0xffffffffu, m, 16);
    float Mx = fmaxf(m, m2);
    float f1 = fexp(m - Mx), f2 = fexp(m2 - Mx);
    #pragma unroll
    for (int cc=0;cc<8;cc++) {
        float d2 = __shfl_xor_sync(0xffffffffu, den[cc], 16);
        float n2 = __shfl_xor_sync(0xffffffffu, num[cc], 16);
        den[cc] = den[cc]*f1 + d2*f2;
        num[cc] = num[cc]*f1 + n2*f2;
    }
    if (half == 0) {
        int qidx = b*MQT + (cls ? (512 + qi) : qi);
        float* pp = g_mpart + (((size_t)qidx*2 + head)*4 + seg)*MREC;
        pp[0] = Mx;
        *(float4*)(pp + 4)  = make_float4(den[0],den[1],den[2],den[3]);
        *(float4*)(pp + 8)  = make_float4(den[4],den[5],den[6],den[7]);
        *(float4*)(pp + 12) = make_float4(num[0],num[1],num[2],num[3]);
        *(float4*)(pp + 16) = make_float4(num[4],num[5],num[6],num[7]);
    }
}

// ---------------- 32->128 projection: merge mta partials + GEMM into merged X ----------
__global__ void proj32_kernel(const float* __restrict__ W, const float* __restrict__ bias,
                              const float* __restrict__ pos, const float* __restrict__ cls_emb)
{
    if (blockIdx.x == 320) {
        for (int i = threadIdx.x; i < 1024; i += 256) {
            int b = i >> 7, j = i & 127;
            float cv = cls_emb[j];
            g_X[((size_t)b*NT1)*128 + j] = cv;
            g_X[((size_t)M1R + (size_t)b*NT2)*128 + j] = cv + pos[j];
        }
        return;
    }
    __shared__ float sWT[128*36];
    __shared__ float sA[16*32];
    const bool cls = blockIdx.x >= 256;
    const int Lq = cls ? 128 : NL;
    const int r0 = (cls ? (blockIdx.x - 256) : blockIdx.x) * 16;
    const int tid = threadIdx.x;
    for (int i = tid; i < 4096; i += 256) {
        int r = i >> 7, c = i & 127;
        sWT[c*36 + r] = W[i];
    }
    // merge mta partials: 256 threads = 16 rows x 2 heads x 8 channels
    {
        const int pr = tid >> 3;           // 0..31 (row, head)
        const int lr = pr >> 1;
        const int head = pr & 1;
        const int cc = tid & 7;
        const int r = r0 + lr;
        const int b = r / Lq, q = r % Lq;
        const int qidx = b*MQT + (cls ? (512 + q) : q);
        const float* pp = g_mpart + ((size_t)qidx*2 + head)*4*MREC;
        float ms = pp[0];
        ms = fmaxf(ms, pp[MREC]);
        ms = fmaxf(ms, pp[2*MREC]);
        ms = fmaxf(ms, pp[3*MREC]);
        float den = 0.f, num = 0.f;
        #pragma unroll
        for (int s=0;s<4;s++) {
            float f = fexp(pp[s*MREC] - ms);
            den = fmaf(pp[s*MREC + 4 + cc],  f, den);
            num = fmaf(pp[s*MREC + 12 + cc], f, num);
        }
        bool ok = den > 0.f;
        sA[lr*32 + head*16 + cc]     = ok ? num/den : 0.f;
        sA[lr*32 + head*16 + 8 + cc] = ok ? 1.f : 0.f;
    }
    __syncthreads();
    #pragma unroll
    for (int u=0;u<8;u++) {
        int oi = tid + u*256;
        int lr = oi >> 7, col = oi & 127;
        int r = r0 + lr;
        float acc = bias[col];
        const float4* wp = (const float4*)&sWT[col*36];
        const float4* ap = (const float4*)&sA[lr*32];
        #pragma unroll
        for (int k8=0;k8<8;k8++) {
            float4 w = wp[k8];
            float4 a = ap[k8];
            acc = fmaf(a.x, w.x, acc);
            acc = fmaf(a.y, w.y, acc);
            acc = fmaf(a.z, w.z, acc);
            acc = fmaf(a.w, w.w, acc);
        }
        int bb = r / Lq, q = r % Lq;
        size_t row;
        if (cls) row = (size_t)bb*NT1 + 1 + q;
        else   { row = (size_t)M1R + (size_t)bb*NT2 + 1 + q; acc += pos[(size_t)(1+q)*128 + col]; }
        g_X[row*128 + col] = acc;
    }
}

// ---------------- tblock attention PARTIALS: key-segmented across blocks ----------------
__global__ void __launch_bounds__(128, 1) tattn_part_kernel()
{
    const int y = blockIdx.y;
    const int part = y >> 4;
    const int bh = y & 15, b = bh >> 1, head = bh & 1;
    const int T = part ? NT2 : NT1;
    const int base = part ? (M1R + b*NT2) : (b*NT1);
    if (blockIdx.x * 64 >= T) return;
    const int seg = blockIdx.z;
    const int nseg = part ? 4 : 1;
    if (seg >= nseg) return;

    const int segStart = seg * SEGL;
    const int segLen = min(SEGL, T - segStart);
    const int half0 = (segLen + 1) >> 1;

    __shared__ float sK[2][2][16][64];   // buf, half, key, dim
    __shared__ float sV[2][2][16][64];

    const int tid = threadIdx.x;
    const int lane = tid & 31, warp = tid >> 5;
    const int qi = blockIdx.x*64 + warp*16 + (lane & 15);
    const int half = lane >> 4;

    float4 qreg[16];
    if (qi < T) {
        const float* qp = g_Q + ((size_t)base + qi)*128 + head*64;
        #pragma unroll
        for (int i=0;i<16;i++) qreg[i] = *(const float4*)(qp + i*4);
    } else {
        #pragma unroll
        for (int i=0;i<16;i++) qreg[i] = make_float4(0.f,0.f,0.f,0.f);
    }
    float m = -1e30f, l = 0.f;
    float o[64];
    #pragma unroll
    for (int d=0;d<64;d++) o[d]=0.f;

    const int myStart = half ? half0 : 0;
    const int myEnd   = half ? segLen : half0;
    const int nch = (half0 + 15) >> 4;

    auto loadChunk = [&](int c, int bf) {
        #pragma unroll
        for (int u=0;u<8;u++) {
            int idx4 = tid*8 + u;
            int isV = idx4 >> 9;
            int r = idx4 & 511;
            int hh = r >> 8, kk = (r >> 4) & 15, d = (r & 15) * 4;
            int klocal = (hh ? half0 : 0) + c*16 + kk;
            int lim = hh ? segLen : half0;
            float4 v = make_float4(0.f,0.f,0.f,0.f);
            if (klocal < lim) {
                const float* src = (isV ? g_V : g_K) +
                    ((size_t)base + segStart + klocal)*128 + head*64 + d;
                v = *(const float4*)src;
            }
            float* dst = (isV ? &sV[bf][hh][kk][d] : &sK[bf][hh][kk][d]);
            *(float4*)dst = v;
        }
    };

    loadChunk(0, 0);
    __syncthreads();
    for (int c=0;c<nch;c++) {
        const int cur = c & 1;
        if (c+1 < nch) loadChunk(c+1, cur^1);
        const int k0 = myStart + c*16;
        const float* sKh = &sK[cur][half][0][0];
        const float* sVh = &sV[cur][half][0][0];
        #pragma unroll 2
        for (int kk=0;kk<16;kk+=2) {
            const float4* kr0 = (const float4*)(sKh + kk*64);
            const float4* kr1 = (const float4*)(sKh + (kk+1)*64);
            float4 A0 = make_float4(0.f,0.f,0.f,0.f);
            float4 A1 = make_float4(0.f,0.f,0.f,0.f);
            #pragma unroll
            for (int i=0;i<16;i++) {
                float4 k0v = kr0[i], k1v = kr1[i];
                float4 q = qreg[i];
                A0.x = fmaf(k0v.x, q.x, A0.x); A1.x = fmaf(k1v.x, q.x, A1.x);
                A0.y = fmaf(k0v.y, q.y, A0.y); A1.y = fmaf(k1v.y, q.y, A1.y);
                A0.z = fmaf(k0v.z, q.z, A0.z); A1.z = fmaf(k1v.z, q.z, A1.z);
                A0.w = fmaf(k0v.w, q.w, A0.w); A1.w = fmaf(k1v.w, q.w, A1.w);
            }
            float s0 = ((A0.x+A0.y)+(A0.z+A0.w))*0.125f;
            float s1 = ((A1.x+A1.y)+(A1.z+A1.w))*0.125f;
            bool v0 = (k0 + kk < myEnd), v1 = (k0 + kk + 1 < myEnd);
            float mx = m;
            if (v0) mx = fmaxf(mx, s0);
            if (v1) mx = fmaxf(mx, s1);
            if (mx > m) {
                float f = fexp(m - mx);
                l *= f;
                #pragma unroll
                for (int d=0;d<64;d++) o[d]*=f;
                m = mx;
            }
            float e0 = v0 ? fexp(s0 - m) : 0.f;
            float e1 = v1 ? fexp(s1 - m) : 0.f;
            l += e0 + e1;
            const float4* vr0 = (const float4*)(sVh + kk*64);
            const float4* vr1 = (const float4*)(sVh + (kk+1)*64);
            #pragma unroll
            for (int i=0;i<16;i++) {
                float4 w0 = vr0[i], w1 = vr1[i];
                o[i*4+0] = fmaf(e0, w0.x, fmaf(e1, w1.x, o[i*4+0]));
                o[i*4+1] = fmaf(e0, w0.y, fmaf(e1, w1.y, o[i*4+1]));
                o[i*4+2] = fmaf(e0, w0.z, fmaf(e1, w1.z, o[i*4+2]));
                o[i*4+3] = fmaf(e0, w0.w, fmaf(e1, w1.w, o[i*4+3]));
            }
        }
        __syncthreads();
    }
    float m2 = __shfl_xor_sync(0xffffffffu, m, 16);
    float Mx = fmaxf(m, m2);
    float f1 = fexp(m - Mx), f2 = fexp(m2 - Mx);
    float l2 = __shfl_xor_sync(0xffffffffu, l, 16);
    l = l*f1 + l2*f2;
    #pragma unroll
    for (int d=0;d<64;d++) {
        float o2 = __shfl_xor_sync(0xffffffffu, o[d], 16);
        o[d] = o[d]*f1 + o2*f2;
    }
    if (half == 0 && qi < T) {
        float* pp = g_part + (((size_t)(base + qi)*2 + head)*4 + seg)*PREC;
        pp[0] = Mx;
        pp[1] = l;
        #pragma unroll
        for (int i=0;i<16;i++)
            *(float4*)(pp + 4 + i*4) = make_float4(o[i*4],o[i*4+1],o[i*4+2],o[i*4+3]);
    }
}

// ---------------- MERGE partials + Wo GEMM + residual + LN1 → X2 ----------------
__global__ void __launch_bounds__(256, 1) merge_ln_kernel(
    const float* __restrict__ tWo, const float* __restrict__ tbo,
    const float* __restrict__ lng, const float* __restrict__ lnb)
{
    extern __shared__ float sm[];
    float* Ws = sm;
    float* As = sm + 128*132;
    float* F  = sm + 128*132 + 4*ACH;

    const int m0 = blockIdx.x * 32;
    const int tid = threadIdx.x;
    const int lane = tid & 31, warp = tid >> 5;
    const int g = lane >> 2, tig = lane & 3;
    const int n0w = warp * 16;

    {
        const int pair = tid >> 2;
        const int lr = pair >> 1;
        const int head = pair & 1;
        const int d0 = (tid & 3) * 16;
        const int r = m0 + lr;
        if (r < MTR) {
            const int nseg = (r < M1R) ? 1 : 4;
            const float* pp = g_part + ((size_t)r*2 + head)*4*PREC;
            float ms = pp[0];
            for (int s=1; s<nseg; s++) ms = fmaxf(ms, pp[s*PREC]);
            float f[4]; float L = 0.f;
            for (int s=0; s<nseg; s++) { f[s] = fexp(pp[s*PREC] - ms); L = fmaf(pp[s*PREC+1], f[s], L); }
            float invL = 1.0f / L;
            for (int dd=0; dd<16; dd++) {
                int d = d0 + dd;
                float acc = 0.f;
                for (int s=0; s<nseg; s++) acc = fmaf(pp[s*PREC + 4 + d], f[s], acc);
                int col = head*64 + d;
                As[(col >> 5)*ACH + lr*36 + (col & 31)] = f2tf(acc * invL);
            }
        } else {
            for (int dd=0; dd<16; dd++) {
                int col = head*64 + d0 + dd;
                As[(col >> 5)*ACH + lr*36 + (col & 31)] = 0.f;
            }
        }
    }
    stage_Wfull(Ws, tWo, tid);
    __syncthreads();

    float acc[2][2][4];
    #pragma unroll
    for (int a=0;a<2;a++)
        #pragma unroll
        for (int b=0;b<2;b++)
            #pragma unroll
            for (int c=0;c<4;c++) acc[a][b][c] = 0.f;

    #pragma unroll
    for (int c4=0;c4<4;c4++)
        mma_chunk(As + c4*ACH, Ws + c4*32*132, n0w, g, tig, acc);
    __syncthreads();

    #pragma unroll
    for (int ni=0;ni<2;ni++) {
        int col = n0w + ni*8 + tig*2;
        float b0 = tbo[col], b1v = tbo[col+1];
        #pragma unroll
        for (int mi=0;mi<2;mi++) {
            int row = mi*16 + g;
            F[row*132 + col]       = acc[mi][ni][0]+b0;
            F[row*132 + col+1]     = acc[mi][ni][1]+b1v;
            F[(row+8)*132 + col]   = acc[mi][ni][2]+b0;
            F[(row+8)*132 + col+1] = acc[mi][ni][3]+b1v;
        }
    }
    __syncthreads();

    float4 g4 = *(const float4*)(lng + lane*4);
    float4 be4 = *(const float4*)(lnb + lane*4);
    #pragma unroll
    for (int i=0;i<4;i++) {
        int row = warp*4 + i;
        int r = m0 + row;
        if (r >= MTR) continue;
        float4 fv = *(const float4*)&F[row*132 + lane*4];
        float4 rv = *(const float4*)(g_X + (size_t)r*128 + lane*4);
        float v[4] = {fv.x+rv.x, fv.y+rv.y, fv.z+rv.z, fv.w+rv.w};
        float s = v[0]+v[1]+v[2]+v[3];
        float s2 = v[0]*v[0]+v[1]*v[1]+v[2]*v[2]+v[3]*v[3];
        #pragma unroll
        for (int off=16; off>0; off>>=1) {
            s  += __shfl_xor_sync(0xffffffffu, s,  off);
            s2 += __shfl_xor_sync(0xffffffffu, s2, off);
        }
        float mean = s * (1.f/128.f);
        float var  = s2 * (1.f/128.f) - mean*mean;
        float rs   = rsqrtf(var + 1e-5f);
        float4 ov;
        ov.x = (v[0]-mean)*rs*g4.x + be4.x;
        ov.y = (v[1]-mean)*rs*g4.y + be4.y;
        ov.z = (v[2]-mean)*rs*g4.z + be4.z;
        ov.w = (v[3]-mean)*rs*g4.w + be4.w;
        *(float4*)(g_X2 + (size_t)r*128 + lane*4) = ov;
    }
}

// ---------------- FUSED FFN (tf32 mma, full staging) + LN2 + inline pooling ----------
__global__ void __launch_bounds__(256, 1) ffn_kernel(
    const float* __restrict__ fW1, const float* __restrict__ fb1,
    const float* __restrict__ fW2, const float* __restrict__ fb2,
    const float* __restrict__ lng, const float* __restrict__ lnb,
    const float* __restrict__ pW, const float* __restrict__ pb,
    float* __restrict__ dpool, float* __restrict__ dlast)
{
    extern __shared__ float sm[];
    float* Ws = sm;
    float* As = sm + 128*132;
    float* F  = sm + 128*132 + 4*ACH;

    const int m0 = blockIdx.x * 32;
    const int tid = threadIdx.x;
    const int lane = tid & 31, warp = tid >> 5;
    const int g = lane >> 2, tig = lane & 3;
    const int n0w = warp * 16;

    float acc[2][2][4];
    #pragma unroll
    for (int a=0;a<2;a++)
        #pragma unroll
        for (int b=0;b<2;b++)
            #pragma unroll
            for (int c=0;c<4;c++) acc[a][b][c] = 0.f;

    #pragma unroll
    for (int u=0;u<4;u++) {
        int e = u*1024 + tid*4;
        int row = e >> 7, col = e & 127;
        int grow = m0 + row;
        float4 a4 = make_float4(0.f,0.f,0.f,0.f);
        if (grow < MTR) a4 = *(const float4*)(g_X2 + (size_t)grow*128 + col);
        int chunk = col >> 5;
        *(float4*)&As[chunk*ACH + row*36 + (col & 31)] =
            make_float4(f2tf(a4.x), f2tf(a4.y), f2tf(a4.z), f2tf(a4.w));
    }
    stage_Wfull(Ws, fW1, tid);
    __syncthreads();

    #pragma unroll
    for (int c4=0;c4<4;c4++)
        mma_chunk(As + c4*ACH, Ws + c4*32*132, n0w, g, tig, acc);
    __syncthreads();

    #pragma unroll
    for (int ni=0;ni<2;ni++) {
        int col = n0w + ni*8 + tig*2;
        float b0 = fb1[col], b1v = fb1[col+1];
        #pragma unroll
        for (int mi=0;mi<2;mi++) {
            int row = mi*16 + g;
            F[row*132 + col]       = f2tf(fmaxf(acc[mi][ni][0]+b0,  0.f));
            F[row*132 + col+1]     = f2tf(fmaxf(acc[mi][ni][1]+b1v, 0.f));
            F[(row+8)*132 + col]   = f2tf(fmaxf(acc[mi][ni][2]+b0,  0.f));
            F[(row+8)*132 + col+1] = f2tf(fmaxf(acc[mi][ni][3]+b1v, 0.f));
        }
    }
    stage_Wfull(Ws, fW2, tid);
    __syncthreads();

    #pragma unroll
    for (int a=0;a<2;a++)
        #pragma unroll
        for (int b=0;b<2;b++)
            #pragma unroll
            for (int c=0;c<4;c++) acc[a][b][c] = 0.f;

    #pragma unroll
    for (int c4=0;c4<4;c4++)
        mma_chunk_F(F, c4*32, Ws + c4*32*132, n0w, g, tig, acc);
    __syncthreads();

    #pragma unroll
    for (int ni=0;ni<2;ni++) {
        int col = n0w + ni*8 + tig*2;
        float b0 = fb2[col], b1v = fb2[col+1];
        #pragma unroll
        for (int mi=0;mi<2;mi++) {
            int row = mi*16 + g;
            F[row*132 + col]       = acc[mi][ni][0]+b0;
            F[row*132 + col+1]     = acc[mi][ni][1]+b1v;
            F[(row+8)*132 + col]   = acc[mi][ni][2]+b0;
            F[(row+8)*132 + col+1] = acc[mi][ni][3]+b1v;
        }
    }
    __syncthreads();

    float4 g4 = *(const float4*)(lng + lane*4);
    float4 be4 = *(const float4*)(lnb + lane*4);
    #pragma unroll
    for (int i=0;i<4;i++) {
        int row = warp*4 + i;
        int r = m0 + row;
        if (r >= MTR) continue;
        float4 fv = *(const float4*)&F[row*132 + lane*4];
        float4 rv = *(const float4*)(g_X2 + (size_t)r*128 + lane*4);
        float v[4] = {fv.x+rv.x, fv.y+rv.y, fv.z+rv.z, fv.w+rv.w};
        float s = v[0]+v[1]+v[2]+v[3];
        float s2 = v[0]*v[0]+v[1]*v[1]+v[2]*v[2]+v[3]*v[3];
        #pragma unroll
        for (int off=16; off>0; off>>=1) {
            s  += __shfl_xor_sync(0xffffffffu, s,  off);
            s2 += __shfl_xor_sync(0xffffffffu, s2, off);
        }
        float mean = s * (1.f/128.f);
        float var  = s2 * (1.f/128.f) - mean*mean;
        float rs   = rsqrtf(var + 1e-5f);
        float4 ov;
        ov.x = (v[0]-mean)*rs*g4.x + be4.x;
        ov.y = (v[1]-mean)*rs*g4.y + be4.y;
        ov.z = (v[2]-mean)*rs*g4.z + be4.z;
        ov.w = (v[3]-mean)*rs*g4.w + be4.w;
        if (r < M1R) {
            if (r % NT1 == 0) {
                int bidx = r / NT1;
                *(float4*)&As[lane*4] = ov;
                __syncwarp();
                float4 accp = *(const float4*)(pb + lane*4);
                for (int k=0;k<128;k++) {
                    float sv = As[k];
                    float4 w = *(const float4*)(pW + (size_t)k*128 + lane*4);
                    accp.x = fmaf(sv, w.x, accp.x);
                    accp.y = fmaf(sv, w.y, accp.y);
                    accp.z = fmaf(sv, w.z, accp.z);
                    accp.w = fmaf(sv, w.w, accp.w);
                }
                float4 outv;
                outv.x = tanhf(accp.x); outv.y = tanhf(accp.y);
                outv.z = tanhf(accp.z); outv.w = tanhf(accp.w);
                *(float4*)(dpool + (size_t)bidx*128 + lane*4) = outv;
            }
        } else {
            int rr = r - M1R;
            int t  = rr % NT2;
            if (t == 0) continue;
            int b  = rr / NT2;
            *(float4*)(dlast + ((size_t)b*NL + t - 1)*128 + lane*4) = ov;
        }
    }
}

// ---------------- launch ----------------
extern "C" void kernel_launch(void* const* d_in, const int* in_sizes, int n_in,
                              void* d_out, int out_size)
{
    (void)in_sizes; (void)n_in; (void)out_size;
    const float* x       = (const float*)d_in[0];
    const float* ts      = (const float*)d_in[1];
    const float* w_per   = (const float*)d_in[2];
    const float* b_per   = (const float*)d_in[3];
    const float* w_lin   = (const float*)d_in[4];
    const float* b_lin   = (const float*)d_in[5];
    const float* Wq_t    = (const float*)d_in[6];
    const float* bq_t    = (const float*)d_in[7];
    const float* Wk_t    = (const float*)d_in[8];
    const float* bk_t    = (const float*)d_in[9];
    const float* Wo_t    = (const float*)d_in[10];
    const float* bo_t    = (const float*)d_in[11];
    const float* pos_emb = (const float*)d_in[12];
    const float* cls_emb = (const float*)d_in[13];
    const float* tWq = (const float*)d_in[14];
    const float* tbq = (const float*)d_in[15];
    const float* tWk = (const float*)d_in[16];
    const float* tbk = (const float*)d_in[17];
    const float* tWv = (const float*)d_in[18];
    const float* tbv = (const float*)d_in[19];
    const float* tWo = (const float*)d_in[20];
    const float* tbo = (const float*)d_in[21];
    const float* ln1_g = (const float*)d_in[22];
    const float* ln1_b = (const float*)d_in[23];
    const float* fW1 = (const float*)d_in[24];
    const float* fb1 = (const float*)d_in[25];
    const float* fW2 = (const float*)d_in[26];
    const float* fb2 = (const float*)d_in[27];
    const float* ln2_g = (const float*)d_in[28];
    const float* ln2_b = (const float*)d_in[29];
    const float* pW  = (const float*)d_in[30];
    const float* pb  = (const float*)d_in[31];
    float* dout = (float*)d_out;

    float *Qb, *Kb, *Qc;
    cudaGetSymbolAddress((void**)&Qb, g_Qb);
    cudaGetSymbolAddress((void**)&Kb, g_Kb);
    cudaGetSymbolAddress((void**)&Qc, g_Qc);

    const int GEMM_SMEM = (128*132 + 4*ACH) * 4;                 // 86016 B
    cudaFuncSetAttribute(kq_gemm_kernel,  cudaFuncAttributeMaxDynamicSharedMemorySize, GEMM_SMEM);
    cudaFuncSetAttribute(qkv_gemm_kernel, cudaFuncAttributeMaxDynamicSharedMemorySize, GEMM_SMEM);
    const int BIG_SMEM = (128*132 + 4*ACH + 32*132) * 4;         // 102912 B
    cudaFuncSetAttribute(merge_ln_kernel, cudaFuncAttributeMaxDynamicSharedMemorySize, BIG_SMEM);
    cudaFuncSetAttribute(ffn_kernel,      cudaFuncAttributeMaxDynamicSharedMemorySize, BIG_SMEM);

    // 1. K/Q projections with inline time-embedding
    kq_gemm_kernel<<<dim3(128, 1, 3), 256, GEMM_SMEM>>>(ts, w_per, b_per, w_lin, b_lin,
                                                        Wq_t, bq_t, Wk_t, bk_t);

    // 2. masked channel attention partials (key-segmented, both heads)
    mta_part_kernel<<<dim3(10, NB, 4), 256>>>(Qb, Qc, Kb, x);

    // 3. merge mta partials + 32->128 projection into merged X (incl. cls rows)
    proj32_kernel<<<321, 256>>>(Wo_t, bo_t, pos_emb, cls_emb);

    // 4. QKV
    qkv_gemm_kernel<<<dim3((MTR+31)/32, 1, 3), 256, GEMM_SMEM>>>(tWq, tbq, tWk, tbk, tWv, tbv);

    // 5a. tblock attention partials, key-segmented across blocks
    tattn_part_kernel<<<dim3((NT2+63)/64, 32, 4), 128>>>();

    // 5b. merge partials + Wo + residual + LN1 → X2
    merge_ln_kernel<<<(MTR+31)/32, 256, BIG_SMEM>>>(tWo, tbo, ln1_g, ln1_b);

    // 6. fused FFN + residual + LN2 + inline cls pooling
    ffn_kernel<<<(MTR+31)/32, 256, BIG_SMEM>>>(fW1, fb1, fW2, fb2, ln2_g, ln2_b,
                                               pW, pb, dout, dout + 1024);
}